// round 3
// baseline (speedup 1.0000x reference)
#include <cuda_runtime.h>

#define NF 256
#define NT 64
#define NDEP 6
#define NTD 384
#define NLEAF 64
#define NU 128
#define NSAMP 16384
#define TS 128
#define NBLK (NSAMP / TS)
#define SMEM_BYTES 180480

// precomputed softmax(feature_logits) over F, layout [f][td]
__device__ float g_sel[NF * NTD];

typedef unsigned long long ull;

__device__ __forceinline__ ull pk2(float lo, float hi) {
    ull r; asm("mov.b64 %0, {%1, %2};" : "=l"(r) : "f"(lo), "f"(hi)); return r;
}
__device__ __forceinline__ void fma2(ull &a, ull x, ull y) {
    asm("fma.rn.f32x2 %0, %1, %2, %0;" : "+l"(a) : "l"(x), "l"(y));
}
__device__ __forceinline__ float2 upk(ull v) {
    float lo, hi; asm("mov.b64 {%0, %1}, %2;" : "=f"(lo), "=f"(hi) : "l"(v));
    return make_float2(lo, hi);
}

// Softmax over the F axis of feature_logits. One block per (t,d) column.
__global__ void prep_kernel(const float* __restrict__ fl) {
    __shared__ float red[8];
    const int td = blockIdx.x;
    const int tid = threadIdx.x;

    float v = fl[tid * NTD + td];

    float m = v;
    #pragma unroll
    for (int o = 16; o; o >>= 1) m = fmaxf(m, __shfl_xor_sync(0xffffffffu, m, o));
    if ((tid & 31) == 0) red[tid >> 5] = m;
    __syncthreads();
    float bm = red[0];
    #pragma unroll
    for (int k = 1; k < 8; k++) bm = fmaxf(bm, red[k]);
    __syncthreads();

    float e = __expf(v - bm);
    float s = e;
    #pragma unroll
    for (int o = 16; o; o >>= 1) s += __shfl_xor_sync(0xffffffffu, s, o);
    if ((tid & 31) == 0) red[tid >> 5] = s;
    __syncthreads();
    float bs = 0.0f;
    #pragma unroll
    for (int k = 0; k < 8; k++) bs += red[k];

    g_sel[tid * NTD + td] = e / bs;
}

// Fused ODT kernel. One block = 128 samples, 256 threads, single wave.
// smem layout (floats):
//   sp   [192][128]   @ 0       (p for half of the trees)         98304 B
//   sx   [64][129]    @ 24576   (x k-chunk, transposed)    \  phase B
//   ssel [64][192]    @ 32832   (selector chunk)           /   82176 B
//   sw   [128][65]    @ 24576   (leaf weights)             \  phase C
//   sr   [64][132]    @ 32896   (response, [c][u])         /   67072 B
__global__ __launch_bounds__(256, 1) void odt_main(
    const float* __restrict__ x, const float* __restrict__ thr,
    const float* __restrict__ logT, const float* __restrict__ resp,
    float* __restrict__ out)
{
    extern __shared__ float smem[];
    float* sp   = smem;
    float* sx   = smem + 24576;
    float* ssel = smem + 32832;
    float* sw   = smem + 24576;
    float* sr   = smem + 32896;

    const int tid = threadIdx.x;
    const int s0  = blockIdx.x * TS;
    const int tyB = tid >> 5, txB = tid & 31;   // phase B: tree-group / sample lane
    const int ty  = tid >> 4, tx  = tid & 15;   // phase C GEMM mapping

    ull acc[8][4];
    #pragma unroll
    for (int i = 0; i < 8; i++)
        #pragma unroll
        for (int j = 0; j < 4; j++) acc[i][j] = 0ull;

    for (int half = 0; half < 2; ++half) {
        // ---------------- Phase B: fv -> sigmoid -> p for 32 trees ----------------
        ull fva[4][4][3];
        #pragma unroll
        for (int a = 0; a < 4; a++)
            #pragma unroll
            for (int b = 0; b < 4; b++)
                #pragma unroll
                for (int c = 0; c < 3; c++) fva[a][b][c] = 0ull;

        for (int kc = 0; kc < 4; ++kc) {
            __syncthreads();  // protects sx/ssel (aliases prev phase-C sw/sr)
            // load x chunk [128 s][64 k] -> sx[k][s] (stride 129, conflict-free)
            #pragma unroll
            for (int it = 0; it < 8; ++it) {
                int idx = tid + it * 256;        // 2048 float4s
                int sl = idx >> 4, k4 = idx & 15;
                float4 v = *(const float4*)(x + (s0 + sl) * NF + kc * 64 + k4 * 4);
                int kk = k4 * 4;
                sx[(kk + 0) * 129 + sl] = v.x;
                sx[(kk + 1) * 129 + sl] = v.y;
                sx[(kk + 2) * 129 + sl] = v.z;
                sx[(kk + 3) * 129 + sl] = v.w;
            }
            // load selector chunk [64 k][192 td]
            #pragma unroll
            for (int it = 0; it < 12; ++it) {
                int idx = tid + it * 256;        // 3072 float4s
                int row = idx / 48, c4 = idx % 48;
                *(float4*)(ssel + row * 192 + c4 * 4) =
                    *(const float4*)(g_sel + (kc * 64 + row) * NTD + half * 192 + c4 * 4);
            }
            __syncthreads();

            #pragma unroll 2
            for (int kk = 0; kk < 64; ++kk) {
                ull xv2[4];
                #pragma unroll
                for (int i = 0; i < 4; i++) {
                    float xv = sx[kk * 129 + i * 32 + txB];
                    xv2[i] = pk2(xv, xv);
                }
                const float* sb = ssel + kk * 192 + tyB * 24;
                #pragma unroll
                for (int tr = 0; tr < 4; tr++) {
                    #pragma unroll
                    for (int dp = 0; dp < 3; dp++) {
                        ull sv = *(const ull*)(sb + tr * 6 + dp * 2);
                        #pragma unroll
                        for (int i = 0; i < 4; i++) fma2(fva[tr][i][dp], xv2[i], sv);
                    }
                }
            }
        }

        // sigmoid((fv - thr) * exp(-logT)) -> sp[td_local][s]
        #pragma unroll
        for (int tr = 0; tr < 4; tr++) {
            int tg = half * 32 + tyB * 4 + tr;
            #pragma unroll
            for (int dp = 0; dp < 3; dp++) {
                #pragma unroll
                for (int d2 = 0; d2 < 2; d2++) {
                    int d = dp * 2 + d2;
                    float tv = thr[tg * NDEP + d];
                    float iv = __expf(-logT[tg * NDEP + d]);
                    #pragma unroll
                    for (int i = 0; i < 4; i++) {
                        float2 f2 = upk(fva[tr][i][dp]);
                        float fv = d2 ? f2.y : f2.x;
                        float tl = (fv - tv) * iv;
                        float pv = __fdividef(1.0f, 1.0f + __expf(-tl));
                        sp[(tyB * 24 + tr * 6 + d) * 128 + i * 32 + txB] = pv;
                    }
                }
            }
        }

        // ---------------- Phase C: per tree, leaf weights + 128x128x64 GEMM ----------------
        for (int tt = 0; tt < 32; ++tt) {
            int t = half * 32 + tt;
            __syncthreads();  // prev GEMM done (or phase B p writes visible)

            // load response[t] [128 u][64 c] -> sr[c][u] (stride 132)
            #pragma unroll
            for (int it = 0; it < 8; ++it) {
                int idx = tid + it * 256;         // 2048 float4s
                int u = idx >> 4, c4 = idx & 15;
                float4 v = *(const float4*)(resp + t * (NU * NLEAF) + u * NLEAF + c4 * 4);
                int c = c4 * 4;
                sr[(c + 0) * 132 + u] = v.x;
                sr[(c + 1) * 132 + u] = v.y;
                sr[(c + 2) * 132 + u] = v.z;
                sr[(c + 3) * 132 + u] = v.w;
            }

            // leaf weights: w[s][c] = prod_d (bit_d(c) ? p_d : 1-p_d)
            {
                int s = tid >> 1, hh = tid & 1;
                const float* pb = sp + tt * 6 * 128 + s;
                float p0 = pb[0],   p1 = pb[128], p2 = pb[256];
                float p3 = pb[384], p4 = pb[512], p5 = pb[640];
                float a0 = 1.f - p0, a1 = 1.f - p1, a2 = 1.f - p2;
                float a3 = 1.f - p3, a4 = 1.f - p4, a5 = 1.f - p5;
                float t0 = a1 * a0, t1 = a1 * p0, t2 = p1 * a0, t3 = p1 * p0;
                float lo[8] = {a2*t0, a2*t1, a2*t2, a2*t3, p2*t0, p2*t1, p2*t2, p2*t3};
                float u0 = a4 * a3, u1 = a4 * p3, u2 = p4 * a3, u3 = p4 * p3;
                float hi[8] = {a5*u0, a5*u1, a5*u2, a5*u3, p5*u0, p5*u1, p5*u2, p5*u3};
                float* wr = sw + s * 65 + hh * 32;
                #pragma unroll
                for (int cc = 0; cc < 32; ++cc)
                    wr[cc] = lo[cc & 7] * hi[hh * 4 + (cc >> 3)];
            }
            __syncthreads();

            // GEMM: acc[s_i][u-pair_j] += w[s][c] * r[c][u0,u1]
            #pragma unroll 4
            for (int c = 0; c < 64; ++c) {
                ull wv2[8];
                #pragma unroll
                for (int i = 0; i < 8; i++) {
                    float w = sw[(i * 16 + ty) * 65 + c];
                    wv2[i] = pk2(w, w);
                }
                ull r2[4];
                #pragma unroll
                for (int j = 0; j < 4; j++)
                    r2[j] = *(const ull*)(sr + c * 132 + j * 32 + 2 * tx);
                #pragma unroll
                for (int i = 0; i < 8; i++)
                    #pragma unroll
                    for (int j = 0; j < 4; j++) fma2(acc[i][j], wv2[i], r2[j]);
            }
        }
    }

    // epilogue: mean over trees (1/64), write float2 per (sample, unit-pair)
    const float sc = 1.0f / 64.0f;
    #pragma unroll
    for (int i = 0; i < 8; i++) {
        int s = i * 16 + ty;
        #pragma unroll
        for (int j = 0; j < 4; j++) {
            float2 v = upk(acc[i][j]);
            float2 o = make_float2(v.x * sc, v.y * sc);
            *(float2*)(out + (s0 + s) * NU + j * 32 + 2 * tx) = o;
        }
    }
}

extern "C" void kernel_launch(void* const* d_in, const int* in_sizes, int n_in,
                              void* d_out, int out_size) {
    const float* x    = (const float*)d_in[0];  // [16,1024,256]
    const float* fl   = (const float*)d_in[1];  // [256,64,6]
    const float* th   = (const float*)d_in[2];  // [64,6]
    const float* lt   = (const float*)d_in[3];  // [64,6]
    const float* rs   = (const float*)d_in[4];  // [64,128,64]
    float* out        = (float*)d_out;          // [16,1024,128]

    cudaFuncSetAttribute(odt_main, cudaFuncAttributeMaxDynamicSharedMemorySize, SMEM_BYTES);

    prep_kernel<<<NTD, 256>>>(fl);
    odt_main<<<NBLK, 256, SMEM_BYTES>>>(x, th, lt, rs, out);
}

// round 5
// speedup vs baseline: 1.6388x; 1.6388x over previous
#include <cuda_runtime.h>
#include <cuda_bf16.h>
#include <cstdint>

#define NF 256
#define NT 64
#define NDEP 6
#define NTD 384
#define NLEAF 64
#define NU 128
#define NSAMP 16384
#define TS 128
#define NBLK (NSAMP / TS)

// ---- smem map (bytes) ----
// sp (fp32 p-values / epilogue staging): [0, 98304)
// phase B overlay: sx [98304,131328), ssel [131328,180480)
// phase C overlay: SWH [98304,114688) SWL [114688,131072)
//                  SRH [131072,147456) SRL [147456,163840)
#define SWH_BYTE 98304
#define SWL_BYTE 114688
#define SRH_BYTE 131072
#define SRL_BYTE 147456
#define SMEM_BYTES 180480

__device__ float g_sel[NF * NTD];
__device__ __nv_bfloat16 g_rhi[NT * NU * NLEAF];
__device__ __nv_bfloat16 g_rlo[NT * NU * NLEAF];

typedef unsigned long long ull;

__device__ __forceinline__ ull pk2(float lo, float hi) {
    ull r; asm("mov.b64 %0, {%1, %2};" : "=l"(r) : "f"(lo), "f"(hi)); return r;
}
__device__ __forceinline__ void fma2(ull &a, ull x, ull y) {
    asm("fma.rn.f32x2 %0, %1, %2, %0;" : "+l"(a) : "l"(x), "l"(y));
}
__device__ __forceinline__ float2 upk(ull v) {
    float lo, hi; asm("mov.b64 {%0, %1}, %2;" : "=f"(lo), "=f"(hi) : "l"(v));
    return make_float2(lo, hi);
}
__device__ __forceinline__ uint32_t cvt2bf(float lo, float hi) {
    uint32_t r; asm("cvt.rn.bf16x2.f32 %0, %1, %2;" : "=r"(r) : "f"(hi), "f"(lo)); return r;
}
__device__ __forceinline__ uint32_t smem_u32(const void* p) {
    uint32_t a;
    asm("{ .reg .u64 t; cvta.to.shared.u64 t, %1; cvt.u32.u64 %0, t; }" : "=r"(a) : "l"(p));
    return a;
}
__device__ __forceinline__ void ldsm4(uint32_t* r, uint32_t addr) {
    asm volatile("ldmatrix.sync.aligned.m8n8.x4.shared.b16 {%0,%1,%2,%3}, [%4];"
                 : "=r"(r[0]), "=r"(r[1]), "=r"(r[2]), "=r"(r[3]) : "r"(addr));
}
__device__ __forceinline__ void mma16816(float* d, const uint32_t* a, uint32_t b0, uint32_t b1) {
    asm volatile(
        "mma.sync.aligned.m16n8k16.row.col.f32.bf16.bf16.f32 "
        "{%0,%1,%2,%3}, {%4,%5,%6,%7}, {%8,%9}, {%0,%1,%2,%3};"
        : "+f"(d[0]), "+f"(d[1]), "+f"(d[2]), "+f"(d[3])
        : "r"(a[0]), "r"(a[1]), "r"(a[2]), "r"(a[3]), "r"(b0), "r"(b1));
}

// ---------------- prep: softmax over F axis of feature_logits ----------------
__global__ void prep_kernel(const float* __restrict__ fl) {
    __shared__ float red[8];
    const int td = blockIdx.x;
    const int tid = threadIdx.x;

    float v = fl[tid * NTD + td];
    float m = v;
    #pragma unroll
    for (int o = 16; o; o >>= 1) m = fmaxf(m, __shfl_xor_sync(0xffffffffu, m, o));
    if ((tid & 31) == 0) red[tid >> 5] = m;
    __syncthreads();
    float bm = red[0];
    #pragma unroll
    for (int k = 1; k < 8; k++) bm = fmaxf(bm, red[k]);
    __syncthreads();
    float e = __expf(v - bm);
    float s = e;
    #pragma unroll
    for (int o = 16; o; o >>= 1) s += __shfl_xor_sync(0xffffffffu, s, o);
    if ((tid & 31) == 0) red[tid >> 5] = s;
    __syncthreads();
    float bs = 0.0f;
    #pragma unroll
    for (int k = 0; k < 8; k++) bs += red[k];
    g_sel[tid * NTD + td] = e / bs;
}

// ---------------- prep: response -> bf16 hi/lo, pre-permuted (XOR-16B swizzle) ----------------
__global__ void prep_resp(const float* __restrict__ resp) {
    int i = blockIdx.x * 256 + threadIdx.x;       // < 64*128*64
    int u = (i >> 6) & 127;
    int c = i & 63;
    float r = resp[i];
    __nv_bfloat16 h = __float2bfloat16(r);
    __nv_bfloat16 l = __float2bfloat16(r - __bfloat162float(h));
    int dst = (i & ~63) | (c ^ ((u & 7) * 8));    // bake the swizzle (8-elem = 16B granule)
    g_rhi[dst] = h;
    g_rlo[dst] = l;
}

// ---------------- main fused kernel ----------------
__global__ __launch_bounds__(256, 1) void odt_main(
    const float* __restrict__ x, const float* __restrict__ thr,
    const float* __restrict__ logT, float* __restrict__ out)
{
    extern __shared__ float smem[];
    char* smemc = (char*)smem;
    float* sp   = smem;
    float* sx   = smem + 24576;
    float* ssel = smem + 32832;

    const int tid = threadIdx.x;
    const int wid = tid >> 5;
    const int lid = tid & 31;
    const int s0  = blockIdx.x * TS;
    const int tyB = wid, txB = lid;
    const uint32_t smem_base = smem_u32(smem);

    // per-thread ldmatrix addressing (XOR-16B swizzle baked into both tiles)
    const uint32_t swz  = (lid & 7) * 16;
    const uint32_t aRow = wid * 16 + (lid & 15);
    const uint32_t aOffH = smem_base + SWH_BYTE + aRow * 128;
    const uint32_t aOffL = smem_base + SWL_BYTE + aRow * 128;
    uint32_t xa[4], xb[4];
    #pragma unroll
    for (int kk = 0; kk < 4; ++kk) {
        xa[kk] = ((uint32_t)(kk * 32) + ((lid >> 4) * 16)) ^ swz;
        xb[kk] = ((uint32_t)(kk * 32) + (((lid >> 3) & 1) * 16)) ^ swz;
    }
    const uint32_t nl0  = (lid & 7) + ((lid >> 4) & 1) * 8;
    const uint32_t bOffH = smem_base + SRH_BYTE + nl0 * 128;
    const uint32_t bOffL = smem_base + SRL_BYTE + nl0 * 128;

    float acc[16][4];
    #pragma unroll
    for (int i = 0; i < 16; i++)
        #pragma unroll
        for (int j = 0; j < 4; j++) acc[i][j] = 0.0f;

    for (int half = 0; half < 2; ++half) {
        // ---------------- Phase B: fv -> sigmoid -> p for 32 trees (fp32) ----------------
        ull fva[4][4][3];
        #pragma unroll
        for (int a = 0; a < 4; a++)
            #pragma unroll
            for (int b = 0; b < 4; b++)
                #pragma unroll
                for (int c = 0; c < 3; c++) fva[a][b][c] = 0ull;

        for (int kc = 0; kc < 4; ++kc) {
            __syncthreads();  // protects sx/ssel (alias prev phase-C tiles)
            #pragma unroll
            for (int it = 0; it < 8; ++it) {
                int idx = tid + it * 256;
                int sl = idx >> 4, k4 = idx & 15;
                float4 v = *(const float4*)(x + (s0 + sl) * NF + kc * 64 + k4 * 4);
                int kk = k4 * 4;
                sx[(kk + 0) * 129 + sl] = v.x;
                sx[(kk + 1) * 129 + sl] = v.y;
                sx[(kk + 2) * 129 + sl] = v.z;
                sx[(kk + 3) * 129 + sl] = v.w;
            }
            #pragma unroll
            for (int it = 0; it < 12; ++it) {
                int idx = tid + it * 256;
                int row = idx / 48, c4 = idx % 48;
                *(float4*)(ssel + row * 192 + c4 * 4) =
                    *(const float4*)(g_sel + (kc * 64 + row) * NTD + half * 192 + c4 * 4);
            }
            __syncthreads();

            #pragma unroll 2
            for (int kk = 0; kk < 64; ++kk) {
                ull xv2[4];
                #pragma unroll
                for (int i = 0; i < 4; i++) {
                    float xv = sx[kk * 129 + i * 32 + txB];
                    xv2[i] = pk2(xv, xv);
                }
                const float* sb = ssel + kk * 192 + tyB * 24;
                #pragma unroll
                for (int tr = 0; tr < 4; tr++) {
                    #pragma unroll
                    for (int dp = 0; dp < 3; dp++) {
                        ull sv = *(const ull*)(sb + tr * 6 + dp * 2);
                        #pragma unroll
                        for (int i = 0; i < 4; i++) fma2(fva[tr][i][dp], xv2[i], sv);
                    }
                }
            }
        }

        #pragma unroll
        for (int tr = 0; tr < 4; tr++) {
            int tg = half * 32 + tyB * 4 + tr;
            #pragma unroll
            for (int dp = 0; dp < 3; dp++) {
                #pragma unroll
                for (int d2 = 0; d2 < 2; d2++) {
                    int d = dp * 2 + d2;
                    float tv = thr[tg * NDEP + d];
                    float iv = __expf(-logT[tg * NDEP + d]);
                    #pragma unroll
                    for (int i = 0; i < 4; i++) {
                        float2 f2 = upk(fva[tr][i][dp]);
                        float fv = d2 ? f2.y : f2.x;
                        float tl = (fv - tv) * iv;
                        float pv = __fdividef(1.0f, 1.0f + __expf(-tl));
                        sp[(tyB * 24 + tr * 6 + d) * 128 + i * 32 + txB] = pv;
                    }
                }
            }
        }
        __syncthreads();   // sp visible to phase C

        // ---------------- Phase C: per tree, leaf weights -> bf16 HMMA (3-pass) ----------------
        for (int tt = 0; tt < 32; ++tt) {
            const int t = half * 32 + tt;
            if (tt) __syncthreads();   // prior tree's ldmatrix reads done

            // copy pre-split, pre-swizzled response tiles
            {
                const uint4* srcH = (const uint4*)(g_rhi + t * (NU * NLEAF));
                const uint4* srcL = (const uint4*)(g_rlo + t * (NU * NLEAF));
                uint4* dstH = (uint4*)(smemc + SRH_BYTE);
                uint4* dstL = (uint4*)(smemc + SRL_BYTE);
                #pragma unroll
                for (int it = 0; it < 4; ++it) {
                    int q = tid + it * 256;
                    dstH[q] = srcH[q];
                    dstL[q] = srcL[q];
                }
            }

            // leaf weights + bf16 hi/lo split -> swizzled SMEM tiles
            {
                int s = tid >> 1, hh = tid & 1;
                const float* pb = sp + tt * 6 * 128 + s;
                float p0 = pb[0],   p1 = pb[128], p2 = pb[256];
                float p3 = pb[384], p4 = pb[512], p5 = pb[640];
                float a0 = 1.f - p0, a1 = 1.f - p1, a2 = 1.f - p2;
                float a3 = 1.f - p3, a4 = 1.f - p4, a5 = 1.f - p5;
                float t0 = a1 * a0, t1 = a1 * p0, t2 = p1 * a0, t3 = p1 * p0;
                float lo8[8] = {a2*t0, a2*t1, a2*t2, a2*t3, p2*t0, p2*t1, p2*t2, p2*t3};
                float u0 = a4 * a3, u1 = a4 * p3, u2 = p4 * a3, u3 = p4 * p3;
                float q5 = hh ? p5 : a5;
                float hv[4] = {q5*u0, q5*u1, q5*u2, q5*u3};

                const int rowoff = s * 128;
                const int swzw = (s & 7) * 16;
                #pragma unroll
                for (int j = 0; j < 16; ++j) {
                    int cc = 2 * j;
                    float w0 = lo8[cc & 7] * hv[cc >> 3];
                    float w1 = lo8[(cc + 1) & 7] * hv[cc >> 3];
                    uint32_t hp = cvt2bf(w0, w1);
                    float l0 = w0 - __int_as_float(hp << 16);
                    float l1 = w1 - __int_as_float(hp & 0xFFFF0000u);
                    uint32_t lp = cvt2bf(l0, l1);
                    int c = hh * 32 + cc;
                    int off = rowoff + ((c * 2) ^ swzw);
                    *(uint32_t*)(smemc + SWH_BYTE + off) = hp;
                    *(uint32_t*)(smemc + SWL_BYTE + off) = lp;
                }
            }
            __syncthreads();

            // A fragments (W hi/lo) for all 4 k-steps
            uint32_t ah[4][4], al[4][4];
            #pragma unroll
            for (int kk = 0; kk < 4; ++kk) {
                ldsm4(ah[kk], aOffH + xa[kk]);
                ldsm4(al[kk], aOffL + xa[kk]);
            }

            // B tiles (R hi/lo), 8 n16-tiles; 3 passes: H·H + H·L + L·H
            #pragma unroll 2
            for (int nt = 0; nt < 8; ++nt) {
                const uint32_t bh_base = bOffH + nt * 2048;
                const uint32_t bl_base = bOffL + nt * 2048;
                #pragma unroll
                for (int kk = 0; kk < 4; ++kk) {
                    uint32_t bh[4], bl[4];
                    ldsm4(bh, bh_base + xb[kk]);
                    ldsm4(bl, bl_base + xb[kk]);
                    mma16816(acc[2*nt],     ah[kk], bh[0], bh[1]);
                    mma16816(acc[2*nt + 1], ah[kk], bh[2], bh[3]);
                    mma16816(acc[2*nt],     ah[kk], bl[0], bl[1]);
                    mma16816(acc[2*nt + 1], ah[kk], bl[2], bl[3]);
                    mma16816(acc[2*nt],     al[kk], bh[0], bh[1]);
                    mma16816(acc[2*nt + 1], al[kk], bh[2], bh[3]);
                }
            }
        }
    }

    // ---------------- epilogue: frags -> smem stage -> coalesced global ----------------
    __syncthreads();   // all tiles/sp reads done; reuse sp as staging
    {
        const float sc = 1.0f / 64.0f;
        const int r0 = wid * 16 + (lid >> 2);
        const int cb = (lid & 3) * 2;
        #pragma unroll
        for (int j = 0; j < 16; ++j) {
            int n = j * 8 + cb;
            sp[r0 * 132 + n]           = acc[j][0] * sc;
            sp[r0 * 132 + n + 1]       = acc[j][1] * sc;
            sp[(r0 + 8) * 132 + n]     = acc[j][2] * sc;
            sp[(r0 + 8) * 132 + n + 1] = acc[j][3] * sc;
        }
    }
    __syncthreads();

    #pragma unroll
    for (int it = 0; it < 16; ++it) {
        int idx = tid + it * 256;
        int s = idx >> 5, u4 = idx & 31;
        float4 v = *(const float4*)(sp + s * 132 + u4 * 4);
        *(float4*)(out + (s0 + s) * NU + u4 * 4) = v;
    }
}

extern "C" void kernel_launch(void* const* d_in, const int* in_sizes, int n_in,
                              void* d_out, int out_size) {
    const float* x  = (const float*)d_in[0];  // [16,1024,256]
    const float* fl = (const float*)d_in[1];  // [256,64,6]
    const float* th = (const float*)d_in[2];  // [64,6]
    const float* lt = (const float*)d_in[3];  // [64,6]
    const float* rs = (const float*)d_in[4];  // [64,128,64]
    float* out      = (float*)d_out;          // [16,1024,128]

    cudaFuncSetAttribute(odt_main, cudaFuncAttributeMaxDynamicSharedMemorySize, SMEM_BYTES);

    prep_kernel<<<NTD, 256>>>(fl);
    prep_resp<<<(NT * NU * NLEAF) / 256, 256>>>(rs);
    odt_main<<<NBLK, 256, SMEM_BYTES>>>(x, th, lt, out);
}

// round 6
// speedup vs baseline: 2.6410x; 1.6115x over previous
#include <cuda_runtime.h>
#include <cuda_bf16.h>
#include <cuda_fp16.h>
#include <cstdint>

#define NF 256
#define NT 64
#define NDEP 6
#define NTD 384
#define NLEAF 64
#define NU 128
#define NSAMP 16384
#define TS 128
#define NBLK (NSAMP / TS)

// ---- smem map (bytes) ----
// sp (fp32 p-values / epilogue staging): [0, 98304)
// phase B overlay: sx [98304,131328), ssel [131328,180480)
// phase C overlay: WBUF0 [98304,114688) WBUF1 [114688,131072)
//                  RBUF0 [131072,147456) RBUF1 [147456,163840)
#define WBUF_BYTE 98304
#define RBUF_BYTE 131072
#define SMEM_BYTES 180480

__device__ float g_sel[NF * NTD];
__device__ __half g_rh[NT * NU * NLEAF];

typedef unsigned long long ull;

__device__ __forceinline__ ull pk2(float lo, float hi) {
    ull r; asm("mov.b64 %0, {%1, %2};" : "=l"(r) : "f"(lo), "f"(hi)); return r;
}
__device__ __forceinline__ void fma2(ull &a, ull x, ull y) {
    asm("fma.rn.f32x2 %0, %1, %2, %0;" : "+l"(a) : "l"(x), "l"(y));
}
__device__ __forceinline__ float2 upk(ull v) {
    float lo, hi; asm("mov.b64 {%0, %1}, %2;" : "=f"(lo), "=f"(hi) : "l"(v));
    return make_float2(lo, hi);
}
__device__ __forceinline__ uint32_t cvt2h(float lo, float hi) {
    uint32_t r; asm("cvt.rn.f16x2.f32 %0, %1, %2;" : "=r"(r) : "f"(hi), "f"(lo)); return r;
}
__device__ __forceinline__ uint32_t smem_u32(const void* p) {
    uint32_t a;
    asm("{ .reg .u64 t; cvta.to.shared.u64 t, %1; cvt.u32.u64 %0, t; }" : "=r"(a) : "l"(p));
    return a;
}
__device__ __forceinline__ void ldsm4(uint32_t* r, uint32_t addr) {
    asm volatile("ldmatrix.sync.aligned.m8n8.x4.shared.b16 {%0,%1,%2,%3}, [%4];"
                 : "=r"(r[0]), "=r"(r[1]), "=r"(r[2]), "=r"(r[3]) : "r"(addr));
}
__device__ __forceinline__ void mma16816(float* d, const uint32_t* a, uint32_t b0, uint32_t b1) {
    asm volatile(
        "mma.sync.aligned.m16n8k16.row.col.f32.f16.f16.f32 "
        "{%0,%1,%2,%3}, {%4,%5,%6,%7}, {%8,%9}, {%0,%1,%2,%3};"
        : "+f"(d[0]), "+f"(d[1]), "+f"(d[2]), "+f"(d[3])
        : "r"(a[0]), "r"(a[1]), "r"(a[2]), "r"(a[3]), "r"(b0), "r"(b1));
}

// ---------------- prep: softmax over F axis of feature_logits ----------------
__global__ void prep_kernel(const float* __restrict__ fl) {
    __shared__ float red[8];
    const int td = blockIdx.x;
    const int tid = threadIdx.x;

    float v = fl[tid * NTD + td];
    float m = v;
    #pragma unroll
    for (int o = 16; o; o >>= 1) m = fmaxf(m, __shfl_xor_sync(0xffffffffu, m, o));
    if ((tid & 31) == 0) red[tid >> 5] = m;
    __syncthreads();
    float bm = red[0];
    #pragma unroll
    for (int k = 1; k < 8; k++) bm = fmaxf(bm, red[k]);
    __syncthreads();
    float e = __expf(v - bm);
    float s = e;
    #pragma unroll
    for (int o = 16; o; o >>= 1) s += __shfl_xor_sync(0xffffffffu, s, o);
    if ((tid & 31) == 0) red[tid >> 5] = s;
    __syncthreads();
    float bs = 0.0f;
    #pragma unroll
    for (int k = 0; k < 8; k++) bs += red[k];
    g_sel[tid * NTD + td] = e / bs;
}

// ---------------- prep: response -> fp16, pre-permuted (XOR-16B swizzle) ----------------
__global__ void prep_resp(const float* __restrict__ resp) {
    int i = blockIdx.x * 256 + threadIdx.x;       // < 64*128*64
    int u = (i >> 6) & 127;
    int c = i & 63;
    int dst = (i & ~63) | (c ^ ((u & 7) * 8));    // bake the swizzle (8-elem = 16B granule)
    g_rh[dst] = __float2half(resp[i]);
}

// leaf weights for one tree -> fp16 swizzled W tile in buffer p
__device__ __forceinline__ void compute_w(char* smemc, const float* sp, int tt, int p, int tid) {
    int s = tid >> 1, hh = tid & 1;
    const float* pb = sp + tt * 6 * 128 + s;
    float p0 = pb[0],   p1 = pb[128], p2 = pb[256];
    float p3 = pb[384], p4 = pb[512], p5 = pb[640];
    float a0 = 1.f - p0, a1 = 1.f - p1, a2 = 1.f - p2;
    float a3 = 1.f - p3, a4 = 1.f - p4, a5 = 1.f - p5;
    float t0 = a1 * a0, t1 = a1 * p0, t2 = p1 * a0, t3 = p1 * p0;
    float lo8[8] = {a2*t0, a2*t1, a2*t2, a2*t3, p2*t0, p2*t1, p2*t2, p2*t3};
    float u0 = a4 * a3, u1 = a4 * p3, u2 = p4 * a3, u3 = p4 * p3;
    float q5 = hh ? p5 : a5;
    float hv[4] = {q5*u0, q5*u1, q5*u2, q5*u3};

    char* wb = smemc + WBUF_BYTE + p * 16384;
    const int rowoff = s * 128;
    const int swzw = (s & 7) * 16;
    #pragma unroll
    for (int j = 0; j < 16; ++j) {
        int cc = 2 * j;
        float w0 = lo8[cc & 7] * hv[cc >> 3];
        float w1 = lo8[(cc + 1) & 7] * hv[cc >> 3];
        uint32_t hp = cvt2h(w0, w1);
        int c = hh * 32 + cc;
        *(uint32_t*)(wb + rowoff + ((c * 2) ^ swzw)) = hp;
    }
}

// ---------------- main fused kernel ----------------
__global__ __launch_bounds__(256, 1) void odt_main(
    const float* __restrict__ x, const float* __restrict__ thr,
    const float* __restrict__ logT, float* __restrict__ out)
{
    extern __shared__ float smem[];
    char* smemc = (char*)smem;
    float* sp   = smem;
    float* sx   = smem + 24576;
    float* ssel = smem + 32832;

    const int tid = threadIdx.x;
    const int wid = tid >> 5;
    const int lid = tid & 31;
    const int s0  = blockIdx.x * TS;
    const int tyB = wid, txB = lid;
    const uint32_t smem_base = smem_u32(smem);

    // 2x2 warp tiling: warp (wm, wn) owns rows [wm*32, +32), cols [wn*64, +64)
    const int wm = wid >> 1, wn = wid & 1;
    const uint32_t swz = (lid & 7) * 16;
    uint32_t xa[4], xb[4];
    #pragma unroll
    for (int kk = 0; kk < 4; ++kk) {
        xa[kk] = ((uint32_t)(kk * 32) + ((lid >> 4) * 16)) ^ swz;
        xb[kk] = ((uint32_t)(kk * 32) + (((lid >> 3) & 1) * 16)) ^ swz;
    }
    const uint32_t aRowOff = (wm * 32 + (lid & 15)) * 128;
    const uint32_t nl0 = (lid & 7) + ((lid >> 4) & 1) * 8;
    const uint32_t bRowOff = (wn * 64 + nl0) * 128;

    float acc[2][8][4];
    #pragma unroll
    for (int m = 0; m < 2; m++)
        #pragma unroll
        for (int i = 0; i < 8; i++)
            #pragma unroll
            for (int j = 0; j < 4; j++) acc[m][i][j] = 0.0f;

    for (int half = 0; half < 2; ++half) {
        // ---------------- Phase B: fv -> sigmoid -> p for 32 trees (fp32) ----------------
        ull fva[4][4][3];
        #pragma unroll
        for (int a = 0; a < 4; a++)
            #pragma unroll
            for (int b = 0; b < 4; b++)
                #pragma unroll
                for (int c = 0; c < 3; c++) fva[a][b][c] = 0ull;

        for (int kc = 0; kc < 4; ++kc) {
            __syncthreads();  // protects sx/ssel (alias phase-C tiles)
            #pragma unroll
            for (int it = 0; it < 8; ++it) {
                int idx = tid + it * 256;
                int sl = idx >> 4, k4 = idx & 15;
                float4 v = *(const float4*)(x + (s0 + sl) * NF + kc * 64 + k4 * 4);
                int kk = k4 * 4;
                sx[(kk + 0) * 129 + sl] = v.x;
                sx[(kk + 1) * 129 + sl] = v.y;
                sx[(kk + 2) * 129 + sl] = v.z;
                sx[(kk + 3) * 129 + sl] = v.w;
            }
            #pragma unroll
            for (int it = 0; it < 12; ++it) {
                int idx = tid + it * 256;
                int row = idx / 48, c4 = idx % 48;
                *(float4*)(ssel + row * 192 + c4 * 4) =
                    *(const float4*)(g_sel + (kc * 64 + row) * NTD + half * 192 + c4 * 4);
            }
            __syncthreads();

            #pragma unroll 2
            for (int kk = 0; kk < 64; ++kk) {
                ull xv2[4];
                #pragma unroll
                for (int i = 0; i < 4; i++) {
                    float xv = sx[kk * 129 + i * 32 + txB];
                    xv2[i] = pk2(xv, xv);
                }
                const float* sb = ssel + kk * 192 + tyB * 24;
                #pragma unroll
                for (int tr = 0; tr < 4; tr++) {
                    #pragma unroll
                    for (int dp = 0; dp < 3; dp++) {
                        ull sv = *(const ull*)(sb + tr * 6 + dp * 2);
                        #pragma unroll
                        for (int i = 0; i < 4; i++) fma2(fva[tr][i][dp], xv2[i], sv);
                    }
                }
            }
        }

        #pragma unroll
        for (int tr = 0; tr < 4; tr++) {
            int tg = half * 32 + tyB * 4 + tr;
            #pragma unroll
            for (int dp = 0; dp < 3; dp++) {
                #pragma unroll
                for (int d2 = 0; d2 < 2; d2++) {
                    int d = dp * 2 + d2;
                    float tv = thr[tg * NDEP + d];
                    float iv = __expf(-logT[tg * NDEP + d]);
                    #pragma unroll
                    for (int i = 0; i < 4; i++) {
                        float2 f2 = upk(fva[tr][i][dp]);
                        float fv = d2 ? f2.y : f2.x;
                        float tl = (fv - tv) * iv;
                        float pv = __fdividef(1.0f, 1.0f + __expf(-tl));
                        sp[(tyB * 24 + tr * 6 + d) * 128 + i * 32 + txB] = pv;
                    }
                }
            }
        }
        __syncthreads();   // sp visible; phase-C buffers free

        // ---------------- Phase C: pipelined per-tree fp16 HMMA ----------------
        // prologue: fill buffer 0 with tree (half*32)
        {
            const uint4* srcR = (const uint4*)(g_rh + (half * 32) * (NU * NLEAF));
            uint4* dstR = (uint4*)(smemc + RBUF_BYTE);
            #pragma unroll
            for (int it = 0; it < 4; ++it) dstR[tid + it * 256] = srcR[tid + it * 256];
            compute_w(smemc, sp, 0, 0, tid);
        }
        __syncthreads();

        for (int tt = 0; tt < 32; ++tt) {
            const int p = tt & 1;
            const uint32_t wbase = smem_base + WBUF_BYTE + p * 16384;
            const uint32_t rbase = smem_base + RBUF_BYTE + p * 16384;

            // prefetch next tree's R into registers (overlaps MMAs below)
            uint4 rr[4];
            if (tt < 31) {
                const uint4* srcR = (const uint4*)(g_rh + (half * 32 + tt + 1) * (NU * NLEAF));
                #pragma unroll
                for (int it = 0; it < 4; ++it) rr[it] = srcR[tid + it * 256];
            }

            // A fragments: 2 m16 tiles x 4 k-steps
            uint32_t af[2][4][4];
            #pragma unroll
            for (int mt = 0; mt < 2; ++mt)
                #pragma unroll
                for (int kk = 0; kk < 4; ++kk)
                    ldsm4(af[mt][kk], wbase + aRowOff + mt * 2048 + xa[kk]);

            // B tiles: 4 n16 tiles x 4 k-steps
            #pragma unroll
            for (int nt = 0; nt < 4; ++nt) {
                const uint32_t bb = rbase + bRowOff + nt * 2048;
                #pragma unroll
                for (int kk = 0; kk < 4; ++kk) {
                    uint32_t bf[4];
                    ldsm4(bf, bb + xb[kk]);
                    mma16816(acc[0][nt * 2],     af[0][kk], bf[0], bf[1]);
                    mma16816(acc[0][nt * 2 + 1], af[0][kk], bf[2], bf[3]);
                    mma16816(acc[1][nt * 2],     af[1][kk], bf[0], bf[1]);
                    mma16816(acc[1][nt * 2 + 1], af[1][kk], bf[2], bf[3]);
                }
            }

            // producer: stage next tree into buffer p^1
            if (tt < 31) {
                uint4* dstR = (uint4*)(smemc + RBUF_BYTE + (p ^ 1) * 16384);
                #pragma unroll
                for (int it = 0; it < 4; ++it) dstR[tid + it * 256] = rr[it];
                compute_w(smemc, sp, tt + 1, p ^ 1, tid);
            }
            __syncthreads();
        }
    }

    // ---------------- epilogue: frags -> smem stage -> coalesced global ----------------
    {
        const float sc = 1.0f / 64.0f;
        const int rbase = wm * 32 + (lid >> 2);
        const int cbase = wn * 64 + (lid & 3) * 2;
        #pragma unroll
        for (int mt = 0; mt < 2; ++mt) {
            int r0 = rbase + mt * 16;
            #pragma unroll
            for (int j = 0; j < 8; ++j) {
                int n = cbase + j * 8;
                sp[r0 * 132 + n]           = acc[mt][j][0] * sc;
                sp[r0 * 132 + n + 1]       = acc[mt][j][1] * sc;
                sp[(r0 + 8) * 132 + n]     = acc[mt][j][2] * sc;
                sp[(r0 + 8) * 132 + n + 1] = acc[mt][j][3] * sc;
            }
        }
    }
    __syncthreads();

    #pragma unroll
    for (int it = 0; it < 16; ++it) {
        int idx = tid + it * 256;
        int s = idx >> 5, u4 = idx & 31;
        float4 v = *(const float4*)(sp + s * 132 + u4 * 4);
        *(float4*)(out + (s0 + s) * NU + u4 * 4) = v;
    }
}

extern "C" void kernel_launch(void* const* d_in, const int* in_sizes, int n_in,
                              void* d_out, int out_size) {
    const float* x  = (const float*)d_in[0];  // [16,1024,256]
    const float* fl = (const float*)d_in[1];  // [256,64,6]
    const float* th = (const float*)d_in[2];  // [64,6]
    const float* lt = (const float*)d_in[3];  // [64,6]
    const float* rs = (const float*)d_in[4];  // [64,128,64]
    float* out      = (float*)d_out;          // [16,1024,128]

    cudaFuncSetAttribute(odt_main, cudaFuncAttributeMaxDynamicSharedMemorySize, SMEM_BYTES);

    prep_kernel<<<NTD, 256>>>(fl);
    prep_resp<<<(NT * NU * NLEAF) / 256, 256>>>(rs);
    odt_main<<<NBLK, 256, SMEM_BYTES>>>(x, th, lt, out);
}

// round 7
// speedup vs baseline: 2.7948x; 1.0583x over previous
#include <cuda_runtime.h>
#include <cuda_bf16.h>
#include <cuda_fp16.h>
#include <cstdint>

#define NF 256
#define NT 64
#define NDEP 6
#define NTD 384
#define NLEAF 64
#define NU 128
#define NSAMP 16384
#define TS 128
#define NBLK (NSAMP / TS)
#define NTHR 512

// ---- smem map (bytes) ----
// sp (fp32 p-values / epilogue staging): [0, 98304)
// phase B overlay: sx [98304,131328), ssel [131328,180480)
// phase C overlay: WBUF0 [98304,114688) WBUF1 [114688,131072)
//                  RBUF0 [131072,147456) RBUF1 [147456,163840)
#define WBUF_BYTE 98304
#define RBUF_BYTE 131072
#define SMEM_BYTES 180480

__device__ float g_sel[NF * NTD];
__device__ __half g_rh[NT * NU * NLEAF];

typedef unsigned long long ull;

__device__ __forceinline__ ull pk2(float lo, float hi) {
    ull r; asm("mov.b64 %0, {%1, %2};" : "=l"(r) : "f"(lo), "f"(hi)); return r;
}
__device__ __forceinline__ void fma2(ull &a, ull x, ull y) {
    asm("fma.rn.f32x2 %0, %1, %2, %0;" : "+l"(a) : "l"(x), "l"(y));
}
__device__ __forceinline__ float2 upk(ull v) {
    float lo, hi; asm("mov.b64 {%0, %1}, %2;" : "=f"(lo), "=f"(hi) : "l"(v));
    return make_float2(lo, hi);
}
__device__ __forceinline__ uint32_t cvt2h(float lo, float hi) {
    uint32_t r; asm("cvt.rn.f16x2.f32 %0, %1, %2;" : "=r"(r) : "f"(hi), "f"(lo)); return r;
}
__device__ __forceinline__ uint32_t smem_u32(const void* p) {
    uint32_t a;
    asm("{ .reg .u64 t; cvta.to.shared.u64 t, %1; cvt.u32.u64 %0, t; }" : "=r"(a) : "l"(p));
    return a;
}
__device__ __forceinline__ void ldsm4(uint32_t* r, uint32_t addr) {
    asm volatile("ldmatrix.sync.aligned.m8n8.x4.shared.b16 {%0,%1,%2,%3}, [%4];"
                 : "=r"(r[0]), "=r"(r[1]), "=r"(r[2]), "=r"(r[3]) : "r"(addr));
}
__device__ __forceinline__ void mma16816(float* d, const uint32_t* a, uint32_t b0, uint32_t b1) {
    asm volatile(
        "mma.sync.aligned.m16n8k16.row.col.f32.f16.f16.f32 "
        "{%0,%1,%2,%3}, {%4,%5,%6,%7}, {%8,%9}, {%0,%1,%2,%3};"
        : "+f"(d[0]), "+f"(d[1]), "+f"(d[2]), "+f"(d[3])
        : "r"(a[0]), "r"(a[1]), "r"(a[2]), "r"(a[3]), "r"(b0), "r"(b1));
}

// ---------------- prep: softmax over F axis of feature_logits ----------------
__global__ void prep_kernel(const float* __restrict__ fl) {
    __shared__ float red[8];
    const int td = blockIdx.x;
    const int tid = threadIdx.x;

    float v = fl[tid * NTD + td];
    float m = v;
    #pragma unroll
    for (int o = 16; o; o >>= 1) m = fmaxf(m, __shfl_xor_sync(0xffffffffu, m, o));
    if ((tid & 31) == 0) red[tid >> 5] = m;
    __syncthreads();
    float bm = red[0];
    #pragma unroll
    for (int k = 1; k < 8; k++) bm = fmaxf(bm, red[k]);
    __syncthreads();
    float e = __expf(v - bm);
    float s = e;
    #pragma unroll
    for (int o = 16; o; o >>= 1) s += __shfl_xor_sync(0xffffffffu, s, o);
    if ((tid & 31) == 0) red[tid >> 5] = s;
    __syncthreads();
    float bs = 0.0f;
    #pragma unroll
    for (int k = 0; k < 8; k++) bs += red[k];
    g_sel[tid * NTD + td] = e / bs;
}

// ---------------- prep: response -> fp16, pre-permuted (XOR-16B swizzle) ----------------
__global__ void prep_resp(const float* __restrict__ resp) {
    int i = blockIdx.x * 256 + threadIdx.x;       // < 64*128*64
    int u = (i >> 6) & 127;
    int c = i & 63;
    int dst = (i & ~63) | (c ^ ((u & 7) * 8));    // bake the swizzle (8-elem = 16B granule)
    g_rh[dst] = __float2half(resp[i]);
}

// leaf weights for one tree -> fp16 swizzled W tile in buffer p (512-thread version)
__device__ __forceinline__ void compute_w(char* smemc, const float* sp, int tt, int p, int tid) {
    int s = tid >> 2, qq = tid & 3;        // s: sample row, qq: leaf bits 4-5
    const float* pb = sp + tt * 6 * 128 + s;
    float p0 = pb[0],   p1 = pb[128], p2 = pb[256];
    float p3 = pb[384], p4 = pb[512], p5 = pb[640];
    float a0 = 1.f - p0, a1 = 1.f - p1, a2 = 1.f - p2;
    float a3 = 1.f - p3, a4 = 1.f - p4, a5 = 1.f - p5;
    float t0 = a1 * a0, t1 = a1 * p0, t2 = p1 * a0, t3 = p1 * p0;
    float lo8[8] = {a2*t0, a2*t1, a2*t2, a2*t3, p2*t0, p2*t1, p2*t2, p2*t3};
    float f4 = (qq & 1) ? p4 : a4;
    float f5 = (qq & 2) ? p5 : a5;
    float f45 = f4 * f5;
    float m0 = a3 * f45, m1 = p3 * f45;

    char* wb = smemc + WBUF_BYTE + p * 16384;
    const int rowoff = s * 128;
    const int swzw = (s & 7) * 16;
    #pragma unroll
    for (int j = 0; j < 8; ++j) {
        int cc = 2 * j;                    // leaf bits 0-3 (cc in 0..15)
        float mm = (cc & 8) ? m1 : m0;
        float w0 = lo8[cc & 7] * mm;
        float w1 = lo8[(cc + 1) & 7] * mm;
        uint32_t hp = cvt2h(w0, w1);
        int col = qq * 16 + cc;
        *(uint32_t*)(wb + rowoff + ((col * 2) ^ swzw)) = hp;
    }
}

// ---------------- main fused kernel ----------------
__global__ __launch_bounds__(NTHR, 1) void odt_main(
    const float* __restrict__ x, const float* __restrict__ thr,
    const float* __restrict__ logT, float* __restrict__ out)
{
    extern __shared__ float smem[];
    char* smemc = (char*)smem;
    float* sp   = smem;
    float* sx   = smem + 24576;
    float* ssel = smem + 32832;

    const int tid = threadIdx.x;
    const int wid = tid >> 5;
    const int lid = tid & 31;
    const int s0  = blockIdx.x * TS;
    const int tyB = wid, txB = lid;        // phase B: warp -> 2 trees (12 td)
    const uint32_t smem_base = smem_u32(smem);

    // 4x4 warp tiling: warp (wm, wn) owns rows [wm*32,+32), cols [wn*32,+32)
    const int wm = wid >> 2, wn = wid & 3;
    const uint32_t swz = (lid & 7) * 16;
    uint32_t xa[4], xb[4];
    #pragma unroll
    for (int kk = 0; kk < 4; ++kk) {
        xa[kk] = ((uint32_t)(kk * 32) + ((lid >> 4) * 16)) ^ swz;
        xb[kk] = ((uint32_t)(kk * 32) + (((lid >> 3) & 1) * 16)) ^ swz;
    }
    const uint32_t aRowOff = (wm * 32 + (lid & 15)) * 128;
    const uint32_t nl0 = (lid & 7) + ((lid >> 4) & 1) * 8;
    const uint32_t bRowOff = (wn * 32 + nl0) * 128;

    float acc[2][4][4];                    // [m16 tile][n8 tile][frag]
    #pragma unroll
    for (int m = 0; m < 2; m++)
        #pragma unroll
        for (int i = 0; i < 4; i++)
            #pragma unroll
            for (int j = 0; j < 4; j++) acc[m][i][j] = 0.0f;

    for (int half = 0; half < 2; ++half) {
        // ---------------- Phase B: fv -> sigmoid -> p for 32 trees (fp32) ----------------
        ull fva[2][4][3];                  // [tree][sample-grp][dp-pair]
        #pragma unroll
        for (int a = 0; a < 2; a++)
            #pragma unroll
            for (int b = 0; b < 4; b++)
                #pragma unroll
                for (int c = 0; c < 3; c++) fva[a][b][c] = 0ull;

        for (int kc = 0; kc < 4; ++kc) {
            __syncthreads();  // protects sx/ssel (alias phase-C tiles)
            #pragma unroll
            for (int it = 0; it < 4; ++it) {
                int idx = tid + it * NTHR;           // 2048 float4s
                int sl = idx >> 4, k4 = idx & 15;
                float4 v = *(const float4*)(x + (s0 + sl) * NF + kc * 64 + k4 * 4);
                int kk = k4 * 4;
                sx[(kk + 0) * 129 + sl] = v.x;
                sx[(kk + 1) * 129 + sl] = v.y;
                sx[(kk + 2) * 129 + sl] = v.z;
                sx[(kk + 3) * 129 + sl] = v.w;
            }
            #pragma unroll
            for (int it = 0; it < 6; ++it) {
                int idx = tid + it * NTHR;           // 3072 float4s
                int row = idx / 48, c4 = idx % 48;
                *(float4*)(ssel + row * 192 + c4 * 4) =
                    *(const float4*)(g_sel + (kc * 64 + row) * NTD + half * 192 + c4 * 4);
            }
            __syncthreads();

            #pragma unroll 2
            for (int kk = 0; kk < 64; ++kk) {
                ull xv2[4];
                #pragma unroll
                for (int i = 0; i < 4; i++) {
                    float xv = sx[kk * 129 + i * 32 + txB];
                    xv2[i] = pk2(xv, xv);
                }
                const float* sb = ssel + kk * 192 + tyB * 12;
                #pragma unroll
                for (int tr = 0; tr < 2; tr++) {
                    #pragma unroll
                    for (int dp = 0; dp < 3; dp++) {
                        ull sv = *(const ull*)(sb + tr * 6 + dp * 2);
                        #pragma unroll
                        for (int i = 0; i < 4; i++) fma2(fva[tr][i][dp], xv2[i], sv);
                    }
                }
            }
        }

        #pragma unroll
        for (int tr = 0; tr < 2; tr++) {
            int tg = half * 32 + tyB * 2 + tr;
            #pragma unroll
            for (int dp = 0; dp < 3; dp++) {
                #pragma unroll
                for (int d2 = 0; d2 < 2; d2++) {
                    int d = dp * 2 + d2;
                    float tv = thr[tg * NDEP + d];
                    float iv = __expf(-logT[tg * NDEP + d]);
                    #pragma unroll
                    for (int i = 0; i < 4; i++) {
                        float2 f2 = upk(fva[tr][i][dp]);
                        float fv = d2 ? f2.y : f2.x;
                        float tl = (fv - tv) * iv;
                        float pv = __fdividef(1.0f, 1.0f + __expf(-tl));
                        sp[(tyB * 12 + tr * 6 + d) * 128 + i * 32 + txB] = pv;
                    }
                }
            }
        }
        __syncthreads();   // sp visible; phase-C buffers free

        // ---------------- Phase C: pipelined per-tree fp16 HMMA ----------------
        // prologue: fill buffer 0 with tree (half*32)
        {
            const uint4* srcR = (const uint4*)(g_rh + (half * 32) * (NU * NLEAF));
            uint4* dstR = (uint4*)(smemc + RBUF_BYTE);
            #pragma unroll
            for (int it = 0; it < 2; ++it) dstR[tid + it * NTHR] = srcR[tid + it * NTHR];
            compute_w(smemc, sp, 0, 0, tid);
        }
        __syncthreads();

        for (int tt = 0; tt < 32; ++tt) {
            const int p = tt & 1;
            const uint32_t wbase = smem_base + WBUF_BYTE + p * 16384;
            const uint32_t rbase = smem_base + RBUF_BYTE + p * 16384;

            // prefetch next tree's R into registers (overlaps MMAs below)
            uint4 rr[2];
            if (tt < 31) {
                const uint4* srcR = (const uint4*)(g_rh + (half * 32 + tt + 1) * (NU * NLEAF));
                #pragma unroll
                for (int it = 0; it < 2; ++it) rr[it] = srcR[tid + it * NTHR];
            }

            // A fragments: 2 m16 tiles x 4 k-steps
            uint32_t af[2][4][4];
            #pragma unroll
            for (int mt = 0; mt < 2; ++mt)
                #pragma unroll
                for (int kk = 0; kk < 4; ++kk)
                    ldsm4(af[mt][kk], wbase + aRowOff + mt * 2048 + xa[kk]);

            // B tiles: 2 n16 tiles x 4 k-steps
            #pragma unroll
            for (int nt = 0; nt < 2; ++nt) {
                const uint32_t bb = rbase + bRowOff + nt * 2048;
                #pragma unroll
                for (int kk = 0; kk < 4; ++kk) {
                    uint32_t bf[4];
                    ldsm4(bf, bb + xb[kk]);
                    mma16816(acc[0][nt * 2],     af[0][kk], bf[0], bf[1]);
                    mma16816(acc[0][nt * 2 + 1], af[0][kk], bf[2], bf[3]);
                    mma16816(acc[1][nt * 2],     af[1][kk], bf[0], bf[1]);
                    mma16816(acc[1][nt * 2 + 1], af[1][kk], bf[2], bf[3]);
                }
            }

            // producer: stage next tree into buffer p^1
            if (tt < 31) {
                uint4* dstR = (uint4*)(smemc + RBUF_BYTE + (p ^ 1) * 16384);
                #pragma unroll
                for (int it = 0; it < 2; ++it) dstR[tid + it * NTHR] = rr[it];
                compute_w(smemc, sp, tt + 1, p ^ 1, tid);
            }
            __syncthreads();
        }
    }

    // ---------------- epilogue: frags -> smem stage -> coalesced global ----------------
    {
        const float sc = 1.0f / 64.0f;
        #pragma unroll
        for (int mt = 0; mt < 2; ++mt) {
            int r0 = wm * 32 + mt * 16 + (lid >> 2);
            #pragma unroll
            for (int n8 = 0; n8 < 4; ++n8) {
                int n = wn * 32 + n8 * 8 + (lid & 3) * 2;
                sp[r0 * 132 + n]           = acc[mt][n8][0] * sc;
                sp[r0 * 132 + n + 1]       = acc[mt][n8][1] * sc;
                sp[(r0 + 8) * 132 + n]     = acc[mt][n8][2] * sc;
                sp[(r0 + 8) * 132 + n + 1] = acc[mt][n8][3] * sc;
            }
        }
    }
    __syncthreads();

    #pragma unroll
    for (int it = 0; it < 8; ++it) {
        int idx = tid + it * NTHR;
        int s = idx >> 5, u4 = idx & 31;
        float4 v = *(const float4*)(sp + s * 132 + u4 * 4);
        *(float4*)(out + (s0 + s) * NU + u4 * 4) = v;
    }
}

extern "C" void kernel_launch(void* const* d_in, const int* in_sizes, int n_in,
                              void* d_out, int out_size) {
    const float* x  = (const float*)d_in[0];  // [16,1024,256]
    const float* fl = (const float*)d_in[1];  // [256,64,6]
    const float* th = (const float*)d_in[2];  // [64,6]
    const float* lt = (const float*)d_in[3];  // [64,6]
    const float* rs = (const float*)d_in[4];  // [64,128,64]
    float* out      = (float*)d_out;          // [16,1024,128]

    cudaFuncSetAttribute(odt_main, cudaFuncAttributeMaxDynamicSharedMemorySize, SMEM_BYTES);

    prep_kernel<<<NTD, 256>>>(fl);
    prep_resp<<<(NT * NU * NLEAF) / 256, 256>>>(rs);
    odt_main<<<NBLK, NTHR, SMEM_BYTES>>>(x, th, lt, out);
}

// round 8
// speedup vs baseline: 3.2635x; 1.1677x over previous
#include <cuda_runtime.h>
#include <cuda_bf16.h>
#include <cuda_fp16.h>
#include <cstdint>

#define NF 256
#define NT 64
#define NDEP 6
#define NTD 384
#define NLEAF 64
#define NU 128
#define NSAMP 16384
#define TS 128
#define NBLK (NSAMP / TS)
#define NTHR 512

// ---- smem map (bytes) ----
// sp (fp32 p-values / epilogue staging): [0, 98304)
// phase B overlay: sx [98304,131328), ssel [131328,180480)
// phase C v2 uses NO smem beyond sp.
#define SMEM_BYTES 180480

__device__ float g_sel[NF * NTD];
// R pre-packed in m16n8k16 B-fragment order:
// uint index = ((((t*4 + wn)*8 + q)*32 + lane)*4 + fi);  m = q*4+fi, slot=m>>1, reg=m&1,
// kk = slot>>2, nt = slot&3, n = wn*32+nt*8+(lane>>2), k = kk*16+(lane&3)*2+reg*8
__device__ uint4 g_rf[NT * 4 * 8 * 32];

typedef unsigned long long ull;

__device__ __forceinline__ ull pk2(float lo, float hi) {
    ull r; asm("mov.b64 %0, {%1, %2};" : "=l"(r) : "f"(lo), "f"(hi)); return r;
}
__device__ __forceinline__ void fma2(ull &a, ull x, ull y) {
    asm("fma.rn.f32x2 %0, %1, %2, %0;" : "+l"(a) : "l"(x), "l"(y));
}
__device__ __forceinline__ float2 upk(ull v) {
    float lo, hi; asm("mov.b64 {%0, %1}, %2;" : "=f"(lo), "=f"(hi) : "l"(v));
    return make_float2(lo, hi);
}
__device__ __forceinline__ uint32_t cvt2h(float lo, float hi) {
    uint32_t r; asm("cvt.rn.f16x2.f32 %0, %1, %2;" : "=r"(r) : "f"(hi), "f"(lo)); return r;
}
__device__ __forceinline__ void mma16816(float* d, const uint32_t* a, uint32_t b0, uint32_t b1) {
    asm volatile(
        "mma.sync.aligned.m16n8k16.row.col.f32.f16.f16.f32 "
        "{%0,%1,%2,%3}, {%4,%5,%6,%7}, {%8,%9}, {%0,%1,%2,%3};"
        : "+f"(d[0]), "+f"(d[1]), "+f"(d[2]), "+f"(d[3])
        : "r"(a[0]), "r"(a[1]), "r"(a[2]), "r"(a[3]), "r"(b0), "r"(b1));
}

// ---------------- prep: softmax over F axis of feature_logits ----------------
__global__ void prep_kernel(const float* __restrict__ fl) {
    __shared__ float red[8];
    const int td = blockIdx.x;
    const int tid = threadIdx.x;

    float v = fl[tid * NTD + td];
    float m = v;
    #pragma unroll
    for (int o = 16; o; o >>= 1) m = fmaxf(m, __shfl_xor_sync(0xffffffffu, m, o));
    if ((tid & 31) == 0) red[tid >> 5] = m;
    __syncthreads();
    float bm = red[0];
    #pragma unroll
    for (int k = 1; k < 8; k++) bm = fmaxf(bm, red[k]);
    __syncthreads();
    float e = __expf(v - bm);
    float s = e;
    #pragma unroll
    for (int o = 16; o; o >>= 1) s += __shfl_xor_sync(0xffffffffu, s, o);
    if ((tid & 31) == 0) red[tid >> 5] = s;
    __syncthreads();
    float bs = 0.0f;
    #pragma unroll
    for (int k = 0; k < 8; k++) bs += red[k];
    g_sel[tid * NTD + td] = e / bs;
}

// ---------------- prep: response -> fp16 B-fragments in lane order ----------------
__global__ void prep_resp(const float* __restrict__ resp) {
    int i = blockIdx.x * 256 + threadIdx.x;   // uint index, < 262144
    int fi   = i & 3;
    int lane = (i >> 2) & 31;
    int q    = (i >> 7) & 7;
    int wn   = (i >> 10) & 3;
    int t    = i >> 12;
    int m    = q * 4 + fi;
    int slot = m >> 1, reg = m & 1;
    int kk   = slot >> 2, nt = slot & 3;
    int n    = wn * 32 + nt * 8 + (lane >> 2);
    int k    = kk * 16 + (lane & 3) * 2 + reg * 8;
    const float* rb = resp + t * (NU * NLEAF) + n * NLEAF + k;
    ((uint32_t*)g_rf)[i] = cvt2h(rb[0], rb[1]);
}

// ---------------- main fused kernel ----------------
__global__ __launch_bounds__(NTHR, 1) void odt_main(
    const float* __restrict__ x, const float* __restrict__ thr,
    const float* __restrict__ logT, float* __restrict__ out)
{
    extern __shared__ float smem[];
    float* sp   = smem;
    float* sx   = smem + 24576;
    float* ssel = smem + 32832;

    const int tid = threadIdx.x;
    const int wid = tid >> 5;
    const int lid = tid & 31;
    const int s0  = blockIdx.x * TS;
    const int tyB = wid, txB = lid;        // phase B: warp -> 2 trees (12 td)

    // 4x4 warp tiling: warp (wm, wn) owns rows [wm*32,+32), cols [wn*32,+32)
    const int wm = wid >> 2, wn = wid & 3;

    float acc[2][4][4];                    // [m16 tile][n8 tile][frag]
    #pragma unroll
    for (int m = 0; m < 2; m++)
        #pragma unroll
        for (int i = 0; i < 4; i++)
            #pragma unroll
            for (int j = 0; j < 4; j++) acc[m][i][j] = 0.0f;

    for (int half = 0; half < 2; ++half) {
        // ---------------- Phase B: fv -> sigmoid -> p for 32 trees (fp32) ----------------
        ull fva[2][4][3];                  // [tree][sample-grp][dp-pair]
        #pragma unroll
        for (int a = 0; a < 2; a++)
            #pragma unroll
            for (int b = 0; b < 4; b++)
                #pragma unroll
                for (int c = 0; c < 3; c++) fva[a][b][c] = 0ull;

        for (int kc = 0; kc < 4; ++kc) {
            __syncthreads();  // prior-phase sp/sx/ssel readers done
            #pragma unroll
            for (int it = 0; it < 4; ++it) {
                int idx = tid + it * NTHR;           // 2048 float4s
                int sl = idx >> 4, k4 = idx & 15;
                float4 v = *(const float4*)(x + (s0 + sl) * NF + kc * 64 + k4 * 4);
                int kk = k4 * 4;
                sx[(kk + 0) * 129 + sl] = v.x;
                sx[(kk + 1) * 129 + sl] = v.y;
                sx[(kk + 2) * 129 + sl] = v.z;
                sx[(kk + 3) * 129 + sl] = v.w;
            }
            #pragma unroll
            for (int it = 0; it < 6; ++it) {
                int idx = tid + it * NTHR;           // 3072 float4s
                int row = idx / 48, c4 = idx % 48;
                *(float4*)(ssel + row * 192 + c4 * 4) =
                    *(const float4*)(g_sel + (kc * 64 + row) * NTD + half * 192 + c4 * 4);
            }
            __syncthreads();

            #pragma unroll 2
            for (int kk = 0; kk < 64; ++kk) {
                ull xv2[4];
                #pragma unroll
                for (int i = 0; i < 4; i++) {
                    float xv = sx[kk * 129 + i * 32 + txB];
                    xv2[i] = pk2(xv, xv);
                }
                const float* sb = ssel + kk * 192 + tyB * 12;
                #pragma unroll
                for (int tr = 0; tr < 2; tr++) {
                    #pragma unroll
                    for (int dp = 0; dp < 3; dp++) {
                        ull sv = *(const ull*)(sb + tr * 6 + dp * 2);
                        #pragma unroll
                        for (int i = 0; i < 4; i++) fma2(fva[tr][i][dp], xv2[i], sv);
                    }
                }
            }
        }

        #pragma unroll
        for (int tr = 0; tr < 2; tr++) {
            int tg = half * 32 + tyB * 2 + tr;
            #pragma unroll
            for (int dp = 0; dp < 3; dp++) {
                #pragma unroll
                for (int d2 = 0; d2 < 2; d2++) {
                    int d = dp * 2 + d2;
                    float tv = thr[tg * NDEP + d];
                    float iv = __expf(-logT[tg * NDEP + d]);
                    #pragma unroll
                    for (int i = 0; i < 4; i++) {
                        float2 f2 = upk(fva[tr][i][dp]);
                        float fv = d2 ? f2.y : f2.x;
                        float tl = (fv - tv) * iv;
                        float pv = __fdividef(1.0f, 1.0f + __expf(-tl));
                        sp[(tyB * 12 + tr * 6 + d) * 128 + i * 32 + txB] = pv;
                    }
                }
            }
        }
        __syncthreads();   // sp complete; phase C reads it

        // ---------------- Phase C v2: warp-independent fp16 HMMA, no smem, no sync ----------------
        for (int tt = 0; tt < 32; ++tt) {
            const int t = half * 32 + tt;

            // B fragments: 8 coalesced LDG.128 (L1-shared across the 4 wm-warps)
            uint4 bv[8];
            const uint4* bp = g_rf + ((size_t)(t * 4 + wn) * 8) * 32 + lid;
            #pragma unroll
            for (int q = 0; q < 8; ++q) bv[q] = bp[q * 32];
            const uint32_t* breg = (const uint32_t*)bv;   // breg[(kk*4+nt)*2 + reg]

            const float* pbase = sp + tt * 6 * 128;

            #pragma unroll
            for (int mt = 0; mt < 2; ++mt) {
                // per-lane leaf-weight tables for its two rows
                float wlo0[2], wlo1[2], m8[2][8];
                #pragma unroll
                for (int rr = 0; rr < 2; ++rr) {
                    const float* pb = pbase + wm * 32 + mt * 16 + (lid >> 2) + rr * 8;
                    float p0 = pb[0],   p1 = pb[128], p2 = pb[256];
                    float p3 = pb[384], p4 = pb[512], p5 = pb[640];
                    float a0 = 1.f - p0, a1 = 1.f - p1, a2 = 1.f - p2;
                    float a3 = 1.f - p3, a4 = 1.f - p4, a5 = 1.f - p5;
                    float f1 = (lid & 1) ? p1 : a1;        // leaf bit1 = lid&1
                    float f2 = (lid & 2) ? p2 : a2;        // leaf bit2 = (lid&2)>>1
                    float f12 = f1 * f2;
                    wlo0[rr] = f12 * a0;
                    wlo1[rr] = f12 * p0;
                    float g0 = a3 * a4, g1 = p3 * a4, g2 = a3 * p4, g3 = p3 * p4;
                    m8[rr][0] = g0 * a5; m8[rr][1] = g1 * a5;
                    m8[rr][2] = g2 * a5; m8[rr][3] = g3 * a5;
                    m8[rr][4] = g0 * p5; m8[rr][5] = g1 * p5;
                    m8[rr][6] = g2 * p5; m8[rr][7] = g3 * p5;
                }
                #pragma unroll
                for (int kk = 0; kk < 4; ++kk) {
                    uint32_t a[4];
                    a[0] = cvt2h(wlo0[0] * m8[0][2*kk],     wlo1[0] * m8[0][2*kk]);
                    a[1] = cvt2h(wlo0[1] * m8[1][2*kk],     wlo1[1] * m8[1][2*kk]);
                    a[2] = cvt2h(wlo0[0] * m8[0][2*kk + 1], wlo1[0] * m8[0][2*kk + 1]);
                    a[3] = cvt2h(wlo0[1] * m8[1][2*kk + 1], wlo1[1] * m8[1][2*kk + 1]);
                    #pragma unroll
                    for (int nt = 0; nt < 4; ++nt) {
                        int m = (kk * 4 + nt) * 2;
                        mma16816(acc[mt][nt], a, breg[m], breg[m + 1]);
                    }
                }
            }
        }
    }

    // ---------------- epilogue: frags -> smem stage -> coalesced global ----------------
    __syncthreads();   // all phase-C sp reads done before staging overwrites sp
    {
        const float sc = 1.0f / 64.0f;
        #pragma unroll
        for (int mt = 0; mt < 2; ++mt) {
            int r0 = wm * 32 + mt * 16 + (lid >> 2);
            #pragma unroll
            for (int n8 = 0; n8 < 4; ++n8) {
                int n = wn * 32 + n8 * 8 + (lid & 3) * 2;
                sp[r0 * 132 + n]           = acc[mt][n8][0] * sc;
                sp[r0 * 132 + n + 1]       = acc[mt][n8][1] * sc;
                sp[(r0 + 8) * 132 + n]     = acc[mt][n8][2] * sc;
                sp[(r0 + 8) * 132 + n + 1] = acc[mt][n8][3] * sc;
            }
        }
    }
    __syncthreads();

    #pragma unroll
    for (int it = 0; it < 8; ++it) {
        int idx = tid + it * NTHR;
        int s = idx >> 5, u4 = idx & 31;
        float4 v = *(const float4*)(sp + s * 132 + u4 * 4);
        *(float4*)(out + (s0 + s) * NU + u4 * 4) = v;
    }
}

extern "C" void kernel_launch(void* const* d_in, const int* in_sizes, int n_in,
                              void* d_out, int out_size) {
    const float* x  = (const float*)d_in[0];  // [16,1024,256]
    const float* fl = (const float*)d_in[1];  // [256,64,6]
    const float* th = (const float*)d_in[2];  // [64,6]
    const float* lt = (const float*)d_in[3];  // [64,6]
    const float* rs = (const float*)d_in[4];  // [64,128,64]
    float* out      = (float*)d_out;          // [16,1024,128]

    cudaFuncSetAttribute(odt_main, cudaFuncAttributeMaxDynamicSharedMemorySize, SMEM_BYTES);

    prep_kernel<<<NTD, 256>>>(fl);
    prep_resp<<<(NT * 4 * 8 * 32 * 4) / 256, 256>>>(rs);
    odt_main<<<NBLK, NTHR, SMEM_BYTES>>>(x, th, lt, out);
}

// round 9
// speedup vs baseline: 4.3030x; 1.3185x over previous
#include <cuda_runtime.h>
#include <cuda_bf16.h>
#include <cuda_fp16.h>
#include <cstdint>

#define NF 256
#define NT 64
#define NDEP 6
#define NTD 384
#define NLEAF 64
#define NU 128
#define NSAMP 16384
#define TS 128
#define NBLK (NSAMP / TS)
#define NTHR 512

// ---- smem map (bytes) ----
// sp (fp32 p-values / epilogue staging): [0, 98304)
// phase B x tiles: XH [98304,114688) XL [114688,131072)
#define XH_BYTE 98304
#define XL_BYTE 114688
#define SMEM_BYTES 131072

__device__ float g_sel[NF * NTD];
__device__ float g_invT[NTD];
// R pre-packed in m16n8k16 B-fragment order (verified R8):
__device__ uint4 g_rf[NT * 4 * 8 * 32];
// sel pre-split bf16 hi/lo in B-fragment order:
// j = ((((h*4+kc)*4+wn)*6+nt)*4+kk)*32+lane ; uint4 = {hi_reg0, hi_reg1, lo_reg0, lo_reg1}
__device__ uint4 g_sf[2 * 4 * 4 * 6 * 4 * 32];

typedef unsigned long long ull;

__device__ __forceinline__ uint32_t cvt2h(float lo, float hi) {
    uint32_t r; asm("cvt.rn.f16x2.f32 %0, %1, %2;" : "=r"(r) : "f"(hi), "f"(lo)); return r;
}
__device__ __forceinline__ uint32_t cvt2bf(float lo, float hi) {
    uint32_t r; asm("cvt.rn.bf16x2.f32 %0, %1, %2;" : "=r"(r) : "f"(hi), "f"(lo)); return r;
}
__device__ __forceinline__ uint32_t smem_u32(const void* p) {
    uint32_t a;
    asm("{ .reg .u64 t; cvta.to.shared.u64 t, %1; cvt.u32.u64 %0, t; }" : "=r"(a) : "l"(p));
    return a;
}
__device__ __forceinline__ void ldsm4(uint32_t* r, uint32_t addr) {
    asm volatile("ldmatrix.sync.aligned.m8n8.x4.shared.b16 {%0,%1,%2,%3}, [%4];"
                 : "=r"(r[0]), "=r"(r[1]), "=r"(r[2]), "=r"(r[3]) : "r"(addr));
}
__device__ __forceinline__ void mma16816(float* d, const uint32_t* a, uint32_t b0, uint32_t b1) {
    asm volatile(
        "mma.sync.aligned.m16n8k16.row.col.f32.f16.f16.f32 "
        "{%0,%1,%2,%3}, {%4,%5,%6,%7}, {%8,%9}, {%0,%1,%2,%3};"
        : "+f"(d[0]), "+f"(d[1]), "+f"(d[2]), "+f"(d[3])
        : "r"(a[0]), "r"(a[1]), "r"(a[2]), "r"(a[3]), "r"(b0), "r"(b1));
}
__device__ __forceinline__ void mma16816bf(float* d, const uint32_t* a, uint32_t b0, uint32_t b1) {
    asm volatile(
        "mma.sync.aligned.m16n8k16.row.col.f32.bf16.bf16.f32 "
        "{%0,%1,%2,%3}, {%4,%5,%6,%7}, {%8,%9}, {%0,%1,%2,%3};"
        : "+f"(d[0]), "+f"(d[1]), "+f"(d[2]), "+f"(d[3])
        : "r"(a[0]), "r"(a[1]), "r"(a[2]), "r"(a[3]), "r"(b0), "r"(b1));
}

// ---------------- prep 1: softmax over F axis of feature_logits ----------------
__global__ void prep_kernel(const float* __restrict__ fl) {
    __shared__ float red[8];
    const int td = blockIdx.x;
    const int tid = threadIdx.x;

    float v = fl[tid * NTD + td];
    float m = v;
    #pragma unroll
    for (int o = 16; o; o >>= 1) m = fmaxf(m, __shfl_xor_sync(0xffffffffu, m, o));
    if ((tid & 31) == 0) red[tid >> 5] = m;
    __syncthreads();
    float bm = red[0];
    #pragma unroll
    for (int k = 1; k < 8; k++) bm = fmaxf(bm, red[k]);
    __syncthreads();
    float e = __expf(v - bm);
    float s = e;
    #pragma unroll
    for (int o = 16; o; o >>= 1) s += __shfl_xor_sync(0xffffffffu, s, o);
    if ((tid & 31) == 0) red[tid >> 5] = s;
    __syncthreads();
    float bs = 0.0f;
    #pragma unroll
    for (int k = 0; k < 8; k++) bs += red[k];
    g_sel[tid * NTD + td] = e / bs;
}

// ---------------- prep 2: resp frags + sel frags + invT ----------------
__global__ void prep2(const float* __restrict__ resp, const float* __restrict__ lt) {
    const int b = blockIdx.x, tx = threadIdx.x;
    if (b < 1024) {
        // resp -> fp16 B-fragments (verified R8)
        int i = b * 256 + tx;                     // < 262144 uint32
        int fi   = i & 3;
        int lane = (i >> 2) & 31;
        int q    = (i >> 7) & 7;
        int wn   = (i >> 10) & 3;
        int t    = i >> 12;
        int m    = q * 4 + fi;
        int slot = m >> 1, reg = m & 1;
        int kk   = slot >> 2, nt = slot & 3;
        int n    = wn * 32 + nt * 8 + (lane >> 2);
        int k    = kk * 16 + (lane & 3) * 2 + reg * 8;
        const float* rb = resp + t * (NU * NLEAF) + n * NLEAF + k;
        ((uint32_t*)g_rf)[i] = cvt2h(rb[0], rb[1]);
    } else {
        int j = (b - 1024) * 256 + tx;            // < 24576 uint4
        if (j < NTD) g_invT[j] = __expf(-lt[j]);
        int lane = j & 31;
        int r = j >> 5;
        int kk = r & 3;  r >>= 2;
        int nt = r % 6;  r /= 6;
        int wn = r & 3;  r >>= 2;
        int kc = r & 3;
        int h  = r >> 2;
        int td = h * 192 + wn * 48 + nt * 8 + (lane >> 2);
        int f0 = kc * 64 + kk * 16 + (lane & 3) * 2;
        float s00 = g_sel[(f0 + 0) * NTD + td], s01 = g_sel[(f0 + 1) * NTD + td];
        float s10 = g_sel[(f0 + 8) * NTD + td], s11 = g_sel[(f0 + 9) * NTD + td];
        uint32_t h0 = cvt2bf(s00, s01);
        uint32_t l0 = cvt2bf(s00 - __int_as_float(h0 << 16),
                             s01 - __int_as_float(h0 & 0xFFFF0000u));
        uint32_t h1 = cvt2bf(s10, s11);
        uint32_t l1 = cvt2bf(s10 - __int_as_float(h1 << 16),
                             s11 - __int_as_float(h1 & 0xFFFF0000u));
        g_sf[j] = make_uint4(h0, h1, l0, l1);
    }
}

// ---------------- main fused kernel ----------------
__global__ __launch_bounds__(NTHR, 1) void odt_main(
    const float* __restrict__ x, const float* __restrict__ thr,
    float* __restrict__ out)
{
    extern __shared__ float smem[];
    char* smemc = (char*)smem;
    float* sp = smem;

    const int tid = threadIdx.x;
    const int wid = tid >> 5;
    const int lid = tid & 31;
    const int s0  = blockIdx.x * TS;
    const uint32_t smem_base = smem_u32(smem);
    const uint32_t xhb = smem_base + XH_BYTE;
    const uint32_t xlb = smem_base + XL_BYTE;

    // 4x4 warp tiling (both phases): warp (wm, wn)
    const int wm = wid >> 2, wn = wid & 3;
    const uint32_t swz = (lid & 7) * 16;
    uint32_t xa[4];
    #pragma unroll
    for (int kk = 0; kk < 4; ++kk)
        xa[kk] = ((uint32_t)(kk * 32) + ((lid >> 4) * 16)) ^ swz;
    const uint32_t aRowOff = (wm * 32 + (lid & 15)) * 128;

    float acc[2][4][4];                    // phase C accumulators (persist)
    #pragma unroll
    for (int m = 0; m < 2; m++)
        #pragma unroll
        for (int i = 0; i < 4; i++)
            #pragma unroll
            for (int j = 0; j < 4; j++) acc[m][i][j] = 0.0f;

    for (int half = 0; half < 2; ++half) {
        // ---------------- Phase B v2: fv via 3-pass bf16 HMMA ----------------
        float accB[2][6][4];
        #pragma unroll
        for (int m = 0; m < 2; m++)
            #pragma unroll
            for (int i = 0; i < 6; i++)
                #pragma unroll
                for (int j = 0; j < 4; j++) accB[m][i][j] = 0.0f;

        for (int kc = 0; kc < 4; ++kc) {
            __syncthreads();   // prior readers of XH/XL (and phase C sp reads half0) done
            // load x chunk [128 s][64 f], split bf16 hi/lo, store swizzled
            #pragma unroll
            for (int it = 0; it < 4; ++it) {
                int idx = tid + it * NTHR;         // 2048 float4
                int row = idx >> 4, c4 = idx & 15;
                float4 v = *(const float4*)(x + (s0 + row) * NF + kc * 64 + c4 * 4);
                int base = row * 128;
                int sz = (row & 7) * 16;
                uint32_t hp0 = cvt2bf(v.x, v.y);
                uint32_t lp0 = cvt2bf(v.x - __int_as_float(hp0 << 16),
                                      v.y - __int_as_float(hp0 & 0xFFFF0000u));
                uint32_t hp1 = cvt2bf(v.z, v.w);
                uint32_t lp1 = cvt2bf(v.z - __int_as_float(hp1 << 16),
                                      v.w - __int_as_float(hp1 & 0xFFFF0000u));
                int o0 = base + ((c4 * 8) ^ sz);
                int o1 = base + ((c4 * 8 + 4) ^ sz);
                *(uint32_t*)(smemc + XH_BYTE + o0) = hp0;
                *(uint32_t*)(smemc + XH_BYTE + o1) = hp1;
                *(uint32_t*)(smemc + XL_BYTE + o0) = lp0;
                *(uint32_t*)(smemc + XL_BYTE + o1) = lp1;
            }
            __syncthreads();

            const uint4* bp = g_sf + ((size_t)(((half * 4 + kc) * 4 + wn) * 6) * 4) * 32 + lid;
            #pragma unroll
            for (int kk = 0; kk < 4; ++kk) {
                #pragma unroll
                for (int mt = 0; mt < 2; ++mt) {
                    uint32_t ah[4], al[4];
                    ldsm4(ah, xhb + aRowOff + mt * 2048 + xa[kk]);
                    ldsm4(al, xlb + aRowOff + mt * 2048 + xa[kk]);
                    #pragma unroll
                    for (int nt = 0; nt < 6; ++nt) {
                        uint4 bq = bp[(nt * 4 + kk) * 32];
                        mma16816bf(accB[mt][nt], ah, bq.x, bq.y);
                        mma16816bf(accB[mt][nt], ah, bq.z, bq.w);
                        mma16816bf(accB[mt][nt], al, bq.x, bq.y);
                    }
                }
            }
        }

        // sigmoid((fv - thr) * invT) -> sp[td_local][row]
        #pragma unroll
        for (int nt = 0; nt < 6; ++nt) {
            int c0 = wn * 48 + nt * 8 + (lid & 3) * 2;     // td within half
            float th0 = thr[half * 192 + c0];
            float th1 = thr[half * 192 + c0 + 1];
            float iv0 = g_invT[half * 192 + c0];
            float iv1 = g_invT[half * 192 + c0 + 1];
            #pragma unroll
            for (int mt = 0; mt < 2; ++mt) {
                #pragma unroll
                for (int rr = 0; rr < 2; ++rr) {
                    int row = wm * 32 + mt * 16 + (lid >> 2) + rr * 8;
                    float f0v = accB[mt][nt][rr * 2];
                    float f1v = accB[mt][nt][rr * 2 + 1];
                    float t0 = (f0v - th0) * iv0;
                    float t1 = (f1v - th1) * iv1;
                    sp[c0 * 128 + row]       = __fdividef(1.0f, 1.0f + __expf(-t0));
                    sp[(c0 + 1) * 128 + row] = __fdividef(1.0f, 1.0f + __expf(-t1));
                }
            }
        }
        __syncthreads();   // sp complete; phase C reads it

        // ---------------- Phase C: warp-independent fp16 HMMA (verified R8) ----------------
        for (int tt = 0; tt < 32; ++tt) {
            const int t = half * 32 + tt;

            uint4 bv[8];
            const uint4* bpc = g_rf + ((size_t)(t * 4 + wn) * 8) * 32 + lid;
            #pragma unroll
            for (int q = 0; q < 8; ++q) bv[q] = bpc[q * 32];
            const uint32_t* breg = (const uint32_t*)bv;

            const float* pbase = sp + tt * 6 * 128;

            #pragma unroll
            for (int mt = 0; mt < 2; ++mt) {
                float wlo0[2], wlo1[2], m8[2][8];
                #pragma unroll
                for (int rr = 0; rr < 2; ++rr) {
                    const float* pb = pbase + wm * 32 + mt * 16 + (lid >> 2) + rr * 8;
                    float p0 = pb[0],   p1 = pb[128], p2 = pb[256];
                    float p3 = pb[384], p4 = pb[512], p5 = pb[640];
                    float a0 = 1.f - p0, a1 = 1.f - p1, a2 = 1.f - p2;
                    float a3 = 1.f - p3, a4 = 1.f - p4, a5 = 1.f - p5;
                    float f1 = (lid & 1) ? p1 : a1;
                    float f2 = (lid & 2) ? p2 : a2;
                    float f12 = f1 * f2;
                    wlo0[rr] = f12 * a0;
                    wlo1[rr] = f12 * p0;
                    float g0 = a3 * a4, g1 = p3 * a4, g2 = a3 * p4, g3 = p3 * p4;
                    m8[rr][0] = g0 * a5; m8[rr][1] = g1 * a5;
                    m8[rr][2] = g2 * a5; m8[rr][3] = g3 * a5;
                    m8[rr][4] = g0 * p5; m8[rr][5] = g1 * p5;
                    m8[rr][6] = g2 * p5; m8[rr][7] = g3 * p5;
                }
                #pragma unroll
                for (int kk = 0; kk < 4; ++kk) {
                    uint32_t a[4];
                    a[0] = cvt2h(wlo0[0] * m8[0][2*kk],     wlo1[0] * m8[0][2*kk]);
                    a[1] = cvt2h(wlo0[1] * m8[1][2*kk],     wlo1[1] * m8[1][2*kk]);
                    a[2] = cvt2h(wlo0[0] * m8[0][2*kk + 1], wlo1[0] * m8[0][2*kk + 1]);
                    a[3] = cvt2h(wlo0[1] * m8[1][2*kk + 1], wlo1[1] * m8[1][2*kk + 1]);
                    #pragma unroll
                    for (int nt = 0; nt < 4; ++nt) {
                        int m = (kk * 4 + nt) * 2;
                        mma16816(acc[mt][nt], a, breg[m], breg[m + 1]);
                    }
                }
            }
        }
    }

    // ---------------- epilogue: frags -> smem stage -> coalesced global ----------------
    __syncthreads();
    {
        const float sc = 1.0f / 64.0f;
        #pragma unroll
        for (int mt = 0; mt < 2; ++mt) {
            int r0 = wm * 32 + mt * 16 + (lid >> 2);
            #pragma unroll
            for (int n8 = 0; n8 < 4; ++n8) {
                int n = wn * 32 + n8 * 8 + (lid & 3) * 2;
                sp[r0 * 132 + n]           = acc[mt][n8][0] * sc;
                sp[r0 * 132 + n + 1]       = acc[mt][n8][1] * sc;
                sp[(r0 + 8) * 132 + n]     = acc[mt][n8][2] * sc;
                sp[(r0 + 8) * 132 + n + 1] = acc[mt][n8][3] * sc;
            }
        }
    }
    __syncthreads();

    #pragma unroll
    for (int it = 0; it < 8; ++it) {
        int idx = tid + it * NTHR;
        int s = idx >> 5, u4 = idx & 31;
        float4 v = *(const float4*)(sp + s * 132 + u4 * 4);
        *(float4*)(out + (s0 + s) * NU + u4 * 4) = v;
    }
}

extern "C" void kernel_launch(void* const* d_in, const int* in_sizes, int n_in,
                              void* d_out, int out_size) {
    const float* x  = (const float*)d_in[0];  // [16,1024,256]
    const float* fl = (const float*)d_in[1];  // [256,64,6]
    const float* th = (const float*)d_in[2];  // [64,6]
    const float* lt = (const float*)d_in[3];  // [64,6]
    const float* rs = (const float*)d_in[4];  // [64,128,64]
    float* out      = (float*)d_out;          // [16,1024,128]

    cudaFuncSetAttribute(odt_main, cudaFuncAttributeMaxDynamicSharedMemorySize, SMEM_BYTES);

    prep_kernel<<<NTD, 256>>>(fl);
    prep2<<<1024 + 96, 256>>>(rs, lt);
    odt_main<<<NBLK, NTHR, SMEM_BYTES>>>(x, th, out);
}

// round 10
// speedup vs baseline: 4.3827x; 1.0185x over previous
#include <cuda_runtime.h>
#include <cuda_bf16.h>
#include <cuda_fp16.h>
#include <cstdint>

#define NF 256
#define NT 64
#define NDEP 6
#define NTD 384
#define NLEAF 64
#define NU 128
#define NSAMP 16384
#define TS 128
#define NBLK (NSAMP / TS)
#define NTHR 512

// ---- smem map (bytes) ----
// sp (fp32 p-values / epilogue staging): [0, 98304)
// phase B x tiles, double-buffered:
//   XH0 [98304,114688) XL0 [114688,131072) XH1 [131072,147456) XL1 [147456,163840)
#define XB_BYTE 98304
#define SMEM_BYTES 163840

__device__ float2 g_thrT[NTD];            // {threshold, exp(-logT)} per td
// R pre-packed in m16n8k16 B-fragment order (verified R8), scaled by 1/64:
__device__ uint4 g_rf[NT * 4 * 8 * 32];
// sel pre-split bf16 hi/lo in B-fragment order (layout verified R9):
// j = ((((h*4+kc)*4+wn)*6+nt)*4+kk)*32+lane ; uint4 = {hi_reg0, hi_reg1, lo_reg0, lo_reg1}
__device__ uint4 g_sf[2 * 4 * 4 * 6 * 4 * 32];

typedef unsigned long long ull;

__device__ __forceinline__ uint32_t cvt2h(float lo, float hi) {
    uint32_t r; asm("cvt.rn.f16x2.f32 %0, %1, %2;" : "=r"(r) : "f"(hi), "f"(lo)); return r;
}
__device__ __forceinline__ uint32_t cvt2bf(float lo, float hi) {
    uint32_t r; asm("cvt.rn.bf16x2.f32 %0, %1, %2;" : "=r"(r) : "f"(hi), "f"(lo)); return r;
}
__device__ __forceinline__ uint32_t smem_u32(const void* p) {
    uint32_t a;
    asm("{ .reg .u64 t; cvta.to.shared.u64 t, %1; cvt.u32.u64 %0, t; }" : "=r"(a) : "l"(p));
    return a;
}
__device__ __forceinline__ void ldsm4(uint32_t* r, uint32_t addr) {
    asm volatile("ldmatrix.sync.aligned.m8n8.x4.shared.b16 {%0,%1,%2,%3}, [%4];"
                 : "=r"(r[0]), "=r"(r[1]), "=r"(r[2]), "=r"(r[3]) : "r"(addr));
}
__device__ __forceinline__ void mma16816(float* d, const uint32_t* a, uint32_t b0, uint32_t b1) {
    asm volatile(
        "mma.sync.aligned.m16n8k16.row.col.f32.f16.f16.f32 "
        "{%0,%1,%2,%3}, {%4,%5,%6,%7}, {%8,%9}, {%0,%1,%2,%3};"
        : "+f"(d[0]), "+f"(d[1]), "+f"(d[2]), "+f"(d[3])
        : "r"(a[0]), "r"(a[1]), "r"(a[2]), "r"(a[3]), "r"(b0), "r"(b1));
}
__device__ __forceinline__ void mma16816bf(float* d, const uint32_t* a, uint32_t b0, uint32_t b1) {
    asm volatile(
        "mma.sync.aligned.m16n8k16.row.col.f32.bf16.bf16.f32 "
        "{%0,%1,%2,%3}, {%4,%5,%6,%7}, {%8,%9}, {%0,%1,%2,%3};"
        : "+f"(d[0]), "+f"(d[1]), "+f"(d[2]), "+f"(d[3])
        : "r"(a[0]), "r"(a[1]), "r"(a[2]), "r"(a[3]), "r"(b0), "r"(b1));
}

// ---------------- prep A: softmax + sel-fragment pack (fused, one block per td) ----------------
__global__ void prep_sel(const float* __restrict__ fl) {
    __shared__ float red[8];
    __shared__ float sval[NF];
    const int td = blockIdx.x;
    const int tid = threadIdx.x;

    float v = fl[tid * NTD + td];
    float m = v;
    #pragma unroll
    for (int o = 16; o; o >>= 1) m = fmaxf(m, __shfl_xor_sync(0xffffffffu, m, o));
    if ((tid & 31) == 0) red[tid >> 5] = m;
    __syncthreads();
    float bm = red[0];
    #pragma unroll
    for (int k = 1; k < 8; k++) bm = fmaxf(bm, red[k]);
    __syncthreads();
    float e = __expf(v - bm);
    float s = e;
    #pragma unroll
    for (int o = 16; o; o >>= 1) s += __shfl_xor_sync(0xffffffffu, s, o);
    if ((tid & 31) == 0) red[tid >> 5] = s;
    __syncthreads();
    float bs = 0.0f;
    #pragma unroll
    for (int k = 0; k < 8; k++) bs += red[k];
    sval[tid] = e / bs;
    __syncthreads();

    if (tid < 64) {
        int kc = tid >> 4, kk = (tid >> 2) & 3, fq = tid & 3;
        int h = td / 192, r = td % 192;
        int wn = r / 48, r2 = r % 48;
        int nt = r2 / 8, lr = r2 % 8;
        int lane = lr * 4 + fq;
        int f0 = kc * 64 + kk * 16 + fq * 2;
        float s00 = sval[f0],     s01 = sval[f0 + 1];
        float s10 = sval[f0 + 8], s11 = sval[f0 + 9];
        uint32_t h0 = cvt2bf(s00, s01);
        uint32_t l0 = cvt2bf(s00 - __int_as_float(h0 << 16),
                             s01 - __int_as_float(h0 & 0xFFFF0000u));
        uint32_t h1 = cvt2bf(s10, s11);
        uint32_t l1 = cvt2bf(s10 - __int_as_float(h1 << 16),
                             s11 - __int_as_float(h1 & 0xFFFF0000u));
        int j = ((((h * 4 + kc) * 4 + wn) * 6 + nt) * 4 + kk) * 32 + lane;
        g_sf[j] = make_uint4(h0, h1, l0, l1);
    }
}

// ---------------- prep B: resp frags (scaled 1/64) + thr/invT table (independent) ----------------
__global__ void prep_resp(const float* __restrict__ resp, const float* __restrict__ th,
                          const float* __restrict__ lt) {
    int i = blockIdx.x * 256 + threadIdx.x;    // < 262144 uint32
    if (i < NTD) g_thrT[i] = make_float2(th[i], __expf(-lt[i]));
    int fi   = i & 3;
    int lane = (i >> 2) & 31;
    int q    = (i >> 7) & 7;
    int wn   = (i >> 10) & 3;
    int t    = i >> 12;
    int m    = q * 4 + fi;
    int slot = m >> 1, reg = m & 1;
    int kk   = slot >> 2, nt = slot & 3;
    int n    = wn * 32 + nt * 8 + (lane >> 2);
    int k    = kk * 16 + (lane & 3) * 2 + reg * 8;
    const float* rb = resp + t * (NU * NLEAF) + n * NLEAF + k;
    const float sc = 1.0f / 64.0f;
    ((uint32_t*)g_rf)[i] = cvt2h(rb[0] * sc, rb[1] * sc);
}

// ---------------- main fused kernel ----------------
__global__ __launch_bounds__(NTHR, 1) void odt_main(
    const float* __restrict__ x, float* __restrict__ out)
{
    extern __shared__ float smem[];
    char* smemc = (char*)smem;
    float* sp = smem;

    const int tid = threadIdx.x;
    const int wid = tid >> 5;
    const int lid = tid & 31;
    const int s0  = blockIdx.x * TS;
    const uint32_t smem_base = smem_u32(smem);

    // 4x4 warp tiling (both phases): warp (wm, wn)
    const int wm = wid >> 2, wn = wid & 3;
    const uint32_t swz = (lid & 7) * 16;
    uint32_t xa[4];
    #pragma unroll
    for (int kk = 0; kk < 4; ++kk)
        xa[kk] = ((uint32_t)(kk * 32) + ((lid >> 4) * 16)) ^ swz;
    const uint32_t aRowOff = (wm * 32 + (lid & 15)) * 128;

    float acc[2][4][4];                    // phase C accumulators (persist)
    #pragma unroll
    for (int m = 0; m < 2; m++)
        #pragma unroll
        for (int i = 0; i < 4; i++)
            #pragma unroll
            for (int j = 0; j < 4; j++) acc[m][i][j] = 0.0f;

    for (int half = 0; half < 2; ++half) {
        // ---------------- Phase B: fv via 3-pass bf16 HMMA, double-buffered ----------------
        float accB[2][6][4];
        #pragma unroll
        for (int m = 0; m < 2; m++)
            #pragma unroll
            for (int i = 0; i < 6; i++)
                #pragma unroll
                for (int j = 0; j < 4; j++) accB[m][i][j] = 0.0f;

        __syncthreads();   // phase C (prev half) ldsm/sp reads done; buffers free
        // prologue: chunk kc=0 -> buffer 0
        #pragma unroll
        for (int it = 0; it < 4; ++it) {
            int idx = tid + it * NTHR;
            int row = idx >> 4, c4 = idx & 15;
            float4 v = *(const float4*)(x + (s0 + row) * NF + c4 * 4);
            int base = row * 128;
            int sz = (row & 7) * 16;
            uint32_t hp0 = cvt2bf(v.x, v.y);
            uint32_t lp0 = cvt2bf(v.x - __int_as_float(hp0 << 16),
                                  v.y - __int_as_float(hp0 & 0xFFFF0000u));
            uint32_t hp1 = cvt2bf(v.z, v.w);
            uint32_t lp1 = cvt2bf(v.z - __int_as_float(hp1 << 16),
                                  v.w - __int_as_float(hp1 & 0xFFFF0000u));
            int o0 = base + ((c4 * 8) ^ sz);
            int o1 = base + ((c4 * 8 + 4) ^ sz);
            *(uint32_t*)(smemc + XB_BYTE + o0) = hp0;
            *(uint32_t*)(smemc + XB_BYTE + o1) = hp1;
            *(uint32_t*)(smemc + XB_BYTE + 16384 + o0) = lp0;
            *(uint32_t*)(smemc + XB_BYTE + 16384 + o1) = lp1;
        }
        __syncthreads();

        for (int kc = 0; kc < 4; ++kc) {
            const uint32_t xhb = smem_base + XB_BYTE + (kc & 1) * 32768;
            const uint32_t xlb = xhb + 16384;

            // prefetch next chunk into registers (overlaps MMA issue below)
            float4 vp[4];
            if (kc < 3) {
                #pragma unroll
                for (int it = 0; it < 4; ++it) {
                    int idx = tid + it * NTHR;
                    int row = idx >> 4, c4 = idx & 15;
                    vp[it] = *(const float4*)(x + (s0 + row) * NF + (kc + 1) * 64 + c4 * 4);
                }
            }

            const uint4* bp = g_sf + ((size_t)(((half * 4 + kc) * 4 + wn) * 6) * 4) * 32 + lid;
            #pragma unroll
            for (int kk = 0; kk < 4; ++kk) {
                #pragma unroll
                for (int mt = 0; mt < 2; ++mt) {
                    uint32_t ah[4], al[4];
                    ldsm4(ah, xhb + aRowOff + mt * 2048 + xa[kk]);
                    ldsm4(al, xlb + aRowOff + mt * 2048 + xa[kk]);
                    #pragma unroll
                    for (int nt = 0; nt < 6; ++nt) {
                        uint4 bq = bp[(nt * 4 + kk) * 32];
                        mma16816bf(accB[mt][nt], ah, bq.x, bq.y);
                        mma16816bf(accB[mt][nt], ah, bq.z, bq.w);
                        mma16816bf(accB[mt][nt], al, bq.x, bq.y);
                    }
                }
            }

            // split + store prefetched chunk into the other buffer
            if (kc < 3) {
                char* dh = smemc + XB_BYTE + ((kc + 1) & 1) * 32768;
                #pragma unroll
                for (int it = 0; it < 4; ++it) {
                    int idx = tid + it * NTHR;
                    int row = idx >> 4, c4 = idx & 15;
                    float4 v = vp[it];
                    int base = row * 128;
                    int sz = (row & 7) * 16;
                    uint32_t hp0 = cvt2bf(v.x, v.y);
                    uint32_t lp0 = cvt2bf(v.x - __int_as_float(hp0 << 16),
                                          v.y - __int_as_float(hp0 & 0xFFFF0000u));
                    uint32_t hp1 = cvt2bf(v.z, v.w);
                    uint32_t lp1 = cvt2bf(v.z - __int_as_float(hp1 << 16),
                                          v.w - __int_as_float(hp1 & 0xFFFF0000u));
                    int o0 = base + ((c4 * 8) ^ sz);
                    int o1 = base + ((c4 * 8 + 4) ^ sz);
                    *(uint32_t*)(dh + o0) = hp0;
                    *(uint32_t*)(dh + o1) = hp1;
                    *(uint32_t*)(dh + 16384 + o0) = lp0;
                    *(uint32_t*)(dh + 16384 + o1) = lp1;
                }
            }
            __syncthreads();
        }

        // sigmoid((fv - thr) * invT) -> sp[td_local][row]
        #pragma unroll
        for (int nt = 0; nt < 6; ++nt) {
            int c0 = wn * 48 + nt * 8 + (lid & 3) * 2;     // td within half
            float4 tt = *(const float4*)&g_thrT[half * 192 + c0];
            #pragma unroll
            for (int mt = 0; mt < 2; ++mt) {
                #pragma unroll
                for (int rr = 0; rr < 2; ++rr) {
                    int row = wm * 32 + mt * 16 + (lid >> 2) + rr * 8;
                    float t0 = (accB[mt][nt][rr * 2]     - tt.x) * tt.y;
                    float t1 = (accB[mt][nt][rr * 2 + 1] - tt.z) * tt.w;
                    sp[c0 * 128 + row]       = __fdividef(1.0f, 1.0f + __expf(-t0));
                    sp[(c0 + 1) * 128 + row] = __fdividef(1.0f, 1.0f + __expf(-t1));
                }
            }
        }
        __syncthreads();   // sp complete; phase C reads it

        // ---------------- Phase C: warp-independent fp16 HMMA (verified R8) ----------------
        for (int tt = 0; tt < 32; ++tt) {
            const int t = half * 32 + tt;

            uint4 bv[8];
            const uint4* bpc = g_rf + ((size_t)(t * 4 + wn) * 8) * 32 + lid;
            #pragma unroll
            for (int q = 0; q < 8; ++q) bv[q] = bpc[q * 32];
            const uint32_t* breg = (const uint32_t*)bv;

            const float* pbase = sp + tt * 6 * 128;

            #pragma unroll
            for (int mt = 0; mt < 2; ++mt) {
                float wlo0[2], wlo1[2], m8[2][8];
                #pragma unroll
                for (int rr = 0; rr < 2; ++rr) {
                    const float* pb = pbase + wm * 32 + mt * 16 + (lid >> 2) + rr * 8;
                    float p0 = pb[0],   p1 = pb[128], p2 = pb[256];
                    float p3 = pb[384], p4 = pb[512], p5 = pb[640];
                    float a0 = 1.f - p0, a1 = 1.f - p1, a2 = 1.f - p2;
                    float a3 = 1.f - p3, a4 = 1.f - p4, a5 = 1.f - p5;
                    float f1 = (lid & 1) ? p1 : a1;
                    float f2 = (lid & 2) ? p2 : a2;
                    float f12 = f1 * f2;
                    wlo0[rr] = f12 * a0;
                    wlo1[rr] = f12 * p0;
                    float g0 = a3 * a4, g1 = p3 * a4, g2 = a3 * p4, g3 = p3 * p4;
                    m8[rr][0] = g0 * a5; m8[rr][1] = g1 * a5;
                    m8[rr][2] = g2 * a5; m8[rr][3] = g3 * a5;
                    m8[rr][4] = g0 * p5; m8[rr][5] = g1 * p5;
                    m8[rr][6] = g2 * p5; m8[rr][7] = g3 * p5;
                }
                #pragma unroll
                for (int kk = 0; kk < 4; ++kk) {
                    uint32_t a[4];
                    a[0] = cvt2h(wlo0[0] * m8[0][2*kk],     wlo1[0] * m8[0][2*kk]);
                    a[1] = cvt2h(wlo0[1] * m8[1][2*kk],     wlo1[1] * m8[1][2*kk]);
                    a[2] = cvt2h(wlo0[0] * m8[0][2*kk + 1], wlo1[0] * m8[0][2*kk + 1]);
                    a[3] = cvt2h(wlo0[1] * m8[1][2*kk + 1], wlo1[1] * m8[1][2*kk + 1]);
                    #pragma unroll
                    for (int nt = 0; nt < 4; ++nt) {
                        int m = (kk * 4 + nt) * 2;
                        mma16816(acc[mt][nt], a, breg[m], breg[m + 1]);
                    }
                }
            }
        }
    }

    // ---------------- epilogue: frags -> smem stage -> coalesced global ----------------
    __syncthreads();
    {
        #pragma unroll
        for (int mt = 0; mt < 2; ++mt) {
            int r0 = wm * 32 + mt * 16 + (lid >> 2);
            #pragma unroll
            for (int n8 = 0; n8 < 4; ++n8) {
                int n = wn * 32 + n8 * 8 + (lid & 3) * 2;
                sp[r0 * 132 + n]           = acc[mt][n8][0];
                sp[r0 * 132 + n + 1]       = acc[mt][n8][1];
                sp[(r0 + 8) * 132 + n]     = acc[mt][n8][2];
                sp[(r0 + 8) * 132 + n + 1] = acc[mt][n8][3];
            }
        }
    }
    __syncthreads();

    #pragma unroll
    for (int it = 0; it < 8; ++it) {
        int idx = tid + it * NTHR;
        int s = idx >> 5, u4 = idx & 31;
        float4 v = *(const float4*)(sp + s * 132 + u4 * 4);
        *(float4*)(out + (s0 + s) * NU + u4 * 4) = v;
    }
}

extern "C" void kernel_launch(void* const* d_in, const int* in_sizes, int n_in,
                              void* d_out, int out_size) {
    const float* x  = (const float*)d_in[0];  // [16,1024,256]
    const float* fl = (const float*)d_in[1];  // [256,64,6]
    const float* th = (const float*)d_in[2];  // [64,6]
    const float* lt = (const float*)d_in[3];  // [64,6]
    const float* rs = (const float*)d_in[4];  // [64,128,64]
    float* out      = (float*)d_out;          // [16,1024,128]

    cudaFuncSetAttribute(odt_main, cudaFuncAttributeMaxDynamicSharedMemorySize, SMEM_BYTES);

    prep_sel<<<NTD, 256>>>(fl);
    prep_resp<<<1024, 256>>>(rs, th, lt);
    odt_main<<<NBLK, NTHR, SMEM_BYTES>>>(x, out);
}

// round 11
// speedup vs baseline: 5.4050x; 1.2333x over previous
#include <cuda_runtime.h>
#include <cuda_bf16.h>
#include <cuda_fp16.h>
#include <cstdint>

#define NF 256
#define NT 64
#define NDEP 6
#define NTD 384
#define NLEAF 64
#define NU 128
#define NSAMP 16384
#define TS 128
#define NBLK (NSAMP / TS)
#define NTHR 512

// ---- smem map (bytes) ----
// sp (fp32 p-values / epilogue staging): [0, 98304)
// phase B x tiles (fp16), double-buffered: X0 [98304,114688) X1 [114688,131072)
#define XB_BYTE 98304
#define SMEM_BYTES 131072

__device__ float2 g_thrT[NTD];            // {threshold, exp(-logT)} per td
// R pre-packed in m16n8k16 B-fragment order (verified R8), scaled by 1/64:
__device__ uint4 g_rf[NT * 4 * 8 * 32];
// sel fp16 B-fragments (single-pass):
// j = ((((h*4+kc)*4+wn)*6+nt)*4+kk)*32+lane ; uint2 = {reg0, reg1}
__device__ uint2 g_sf[2 * 4 * 4 * 6 * 4 * 32];

__device__ __forceinline__ uint32_t cvt2h(float lo, float hi) {
    uint32_t r; asm("cvt.rn.f16x2.f32 %0, %1, %2;" : "=r"(r) : "f"(hi), "f"(lo)); return r;
}
__device__ __forceinline__ uint32_t smem_u32(const void* p) {
    uint32_t a;
    asm("{ .reg .u64 t; cvta.to.shared.u64 t, %1; cvt.u32.u64 %0, t; }" : "=r"(a) : "l"(p));
    return a;
}
__device__ __forceinline__ void ldsm4(uint32_t* r, uint32_t addr) {
    asm volatile("ldmatrix.sync.aligned.m8n8.x4.shared.b16 {%0,%1,%2,%3}, [%4];"
                 : "=r"(r[0]), "=r"(r[1]), "=r"(r[2]), "=r"(r[3]) : "r"(addr));
}
__device__ __forceinline__ void mma16816(float* d, const uint32_t* a, uint32_t b0, uint32_t b1) {
    asm volatile(
        "mma.sync.aligned.m16n8k16.row.col.f32.f16.f16.f32 "
        "{%0,%1,%2,%3}, {%4,%5,%6,%7}, {%8,%9}, {%0,%1,%2,%3};"
        : "+f"(d[0]), "+f"(d[1]), "+f"(d[2]), "+f"(d[3])
        : "r"(a[0]), "r"(a[1]), "r"(a[2]), "r"(a[3]), "r"(b0), "r"(b1));
}

// ---------------- prep A: softmax + fp16 sel-fragment pack (one block per td) ----------------
__global__ void prep_sel(const float* __restrict__ fl) {
    __shared__ float red[8];
    __shared__ float sval[NF];
    const int td = blockIdx.x;
    const int tid = threadIdx.x;

    float v = fl[tid * NTD + td];
    float m = v;
    #pragma unroll
    for (int o = 16; o; o >>= 1) m = fmaxf(m, __shfl_xor_sync(0xffffffffu, m, o));
    if ((tid & 31) == 0) red[tid >> 5] = m;
    __syncthreads();
    float bm = red[0];
    #pragma unroll
    for (int k = 1; k < 8; k++) bm = fmaxf(bm, red[k]);
    __syncthreads();
    float e = __expf(v - bm);
    float s = e;
    #pragma unroll
    for (int o = 16; o; o >>= 1) s += __shfl_xor_sync(0xffffffffu, s, o);
    if ((tid & 31) == 0) red[tid >> 5] = s;
    __syncthreads();
    float bs = 0.0f;
    #pragma unroll
    for (int k = 0; k < 8; k++) bs += red[k];
    sval[tid] = e / bs;
    __syncthreads();

    if (tid < 64) {
        int kc = tid >> 4, kk = (tid >> 2) & 3, fq = tid & 3;
        int h = td / 192, r = td % 192;
        int wn = r / 48, r2 = r % 48;
        int nt = r2 / 8, lr = r2 % 8;
        int lane = lr * 4 + fq;
        int f0 = kc * 64 + kk * 16 + fq * 2;
        uint32_t h0 = cvt2h(sval[f0],     sval[f0 + 1]);
        uint32_t h1 = cvt2h(sval[f0 + 8], sval[f0 + 9]);
        int j = ((((h * 4 + kc) * 4 + wn) * 6 + nt) * 4 + kk) * 32 + lane;
        g_sf[j] = make_uint2(h0, h1);
    }
}

// ---------------- prep B: resp frags (scaled 1/64) + thr/invT table ----------------
__global__ void prep_resp(const float* __restrict__ resp, const float* __restrict__ th,
                          const float* __restrict__ lt) {
    int i = blockIdx.x * 256 + threadIdx.x;    // < 262144 uint32
    if (i < NTD) g_thrT[i] = make_float2(th[i], __expf(-lt[i]));
    int fi   = i & 3;
    int lane = (i >> 2) & 31;
    int q    = (i >> 7) & 7;
    int wn   = (i >> 10) & 3;
    int t    = i >> 12;
    int m    = q * 4 + fi;
    int slot = m >> 1, reg = m & 1;
    int kk   = slot >> 2, nt = slot & 3;
    int n    = wn * 32 + nt * 8 + (lane >> 2);
    int k    = kk * 16 + (lane & 3) * 2 + reg * 8;
    const float* rb = resp + t * (NU * NLEAF) + n * NLEAF + k;
    const float sc = 1.0f / 64.0f;
    ((uint32_t*)g_rf)[i] = cvt2h(rb[0] * sc, rb[1] * sc);
}

// ---------------- main fused kernel ----------------
__global__ __launch_bounds__(NTHR, 1) void odt_main(
    const float* __restrict__ x, float* __restrict__ out)
{
    extern __shared__ float smem[];
    char* smemc = (char*)smem;
    float* sp = smem;

    const int tid = threadIdx.x;
    const int wid = tid >> 5;
    const int lid = tid & 31;
    const int s0  = blockIdx.x * TS;
    const uint32_t smem_base = smem_u32(smem);

    // 4x4 warp tiling (both phases): warp (wm, wn)
    const int wm = wid >> 2, wn = wid & 3;
    const uint32_t swz = (lid & 7) * 16;
    uint32_t xa[4];
    #pragma unroll
    for (int kk = 0; kk < 4; ++kk)
        xa[kk] = ((uint32_t)(kk * 32) + ((lid >> 4) * 16)) ^ swz;
    const uint32_t aRowOff = (wm * 32 + (lid & 15)) * 128;

    float acc[2][4][4];                    // phase C accumulators (persist)
    #pragma unroll
    for (int m = 0; m < 2; m++)
        #pragma unroll
        for (int i = 0; i < 4; i++)
            #pragma unroll
            for (int j = 0; j < 4; j++) acc[m][i][j] = 0.0f;

    for (int half = 0; half < 2; ++half) {
        // ---------------- Phase B: fv via single-pass fp16 HMMA ----------------
        float accB[2][6][4];
        #pragma unroll
        for (int m = 0; m < 2; m++)
            #pragma unroll
            for (int i = 0; i < 6; i++)
                #pragma unroll
                for (int j = 0; j < 4; j++) accB[m][i][j] = 0.0f;

        for (int kc = 0; kc < 4; ++kc) {
            const uint32_t xhb = smem_base + XB_BYTE + (kc & 1) * 16384;
            __syncthreads();   // prior readers of this buffer done
            // load x chunk [128 s][64 f] -> fp16 swizzled tile
            #pragma unroll
            for (int it = 0; it < 4; ++it) {
                int idx = tid + it * NTHR;         // 2048 float4
                int row = idx >> 4, c4 = idx & 15;
                float4 v = *(const float4*)(x + (s0 + row) * NF + kc * 64 + c4 * 4);
                int base = row * 128;
                int sz = (row & 7) * 16;
                uint32_t hp0 = cvt2h(v.x, v.y);
                uint32_t hp1 = cvt2h(v.z, v.w);
                char* dh = smemc + XB_BYTE + (kc & 1) * 16384;
                *(uint32_t*)(dh + base + ((c4 * 8) ^ sz))     = hp0;
                *(uint32_t*)(dh + base + ((c4 * 8 + 4) ^ sz)) = hp1;
            }
            __syncthreads();

            const uint2* bp = g_sf + ((size_t)(((half * 4 + kc) * 4 + wn) * 6) * 4) * 32 + lid;
            #pragma unroll
            for (int kk = 0; kk < 4; ++kk) {
                uint2 bq[6];
                #pragma unroll
                for (int nt = 0; nt < 6; ++nt) bq[nt] = bp[(nt * 4 + kk) * 32];
                #pragma unroll
                for (int mt = 0; mt < 2; ++mt) {
                    uint32_t ah[4];
                    ldsm4(ah, xhb + aRowOff + mt * 2048 + xa[kk]);
                    #pragma unroll
                    for (int nt = 0; nt < 6; ++nt)
                        mma16816(accB[mt][nt], ah, bq[nt].x, bq[nt].y);
                }
            }
        }

        // sigmoid((fv - thr) * invT) -> sp[td_local][row]
        #pragma unroll
        for (int nt = 0; nt < 6; ++nt) {
            int c0 = wn * 48 + nt * 8 + (lid & 3) * 2;     // td within half
            float4 tt = *(const float4*)&g_thrT[half * 192 + c0];
            #pragma unroll
            for (int mt = 0; mt < 2; ++mt) {
                #pragma unroll
                for (int rr = 0; rr < 2; ++rr) {
                    int row = wm * 32 + mt * 16 + (lid >> 2) + rr * 8;
                    float t0 = (accB[mt][nt][rr * 2]     - tt.x) * tt.y;
                    float t1 = (accB[mt][nt][rr * 2 + 1] - tt.z) * tt.w;
                    sp[c0 * 128 + row]       = __fdividef(1.0f, 1.0f + __expf(-t0));
                    sp[(c0 + 1) * 128 + row] = __fdividef(1.0f, 1.0f + __expf(-t1));
                }
            }
        }
        __syncthreads();   // sp complete; phase C reads it

        // ---------------- Phase C: warp-independent fp16 HMMA (verified R8) ----------------
        for (int tt = 0; tt < 32; ++tt) {
            const int t = half * 32 + tt;

            uint4 bv[8];
            const uint4* bpc = g_rf + ((size_t)(t * 4 + wn) * 8) * 32 + lid;
            #pragma unroll
            for (int q = 0; q < 8; ++q) bv[q] = bpc[q * 32];
            const uint32_t* breg = (const uint32_t*)bv;

            const float* pbase = sp + tt * 6 * 128;

            #pragma unroll
            for (int mt = 0; mt < 2; ++mt) {
                float wlo0[2], wlo1[2], m8[2][8];
                #pragma unroll
                for (int rr = 0; rr < 2; ++rr) {
                    const float* pb = pbase + wm * 32 + mt * 16 + (lid >> 2) + rr * 8;
                    float p0 = pb[0],   p1 = pb[128], p2 = pb[256];
                    float p3 = pb[384], p4 = pb[512], p5 = pb[640];
                    float a0 = 1.f - p0, a1 = 1.f - p1, a2 = 1.f - p2;
                    float a3 = 1.f - p3, a4 = 1.f - p4, a5 = 1.f - p5;
                    float f1 = (lid & 1) ? p1 : a1;
                    float f2 = (lid & 2) ? p2 : a2;
                    float f12 = f1 * f2;
                    wlo0[rr] = f12 * a0;
                    wlo1[rr] = f12 * p0;
                    float g0 = a3 * a4, g1 = p3 * a4, g2 = a3 * p4, g3 = p3 * p4;
                    m8[rr][0] = g0 * a5; m8[rr][1] = g1 * a5;
                    m8[rr][2] = g2 * a5; m8[rr][3] = g3 * a5;
                    m8[rr][4] = g0 * p5; m8[rr][5] = g1 * p5;
                    m8[rr][6] = g2 * p5; m8[rr][7] = g3 * p5;
                }
                #pragma unroll
                for (int kk = 0; kk < 4; ++kk) {
                    uint32_t a[4];
                    a[0] = cvt2h(wlo0[0] * m8[0][2*kk],     wlo1[0] * m8[0][2*kk]);
                    a[1] = cvt2h(wlo0[1] * m8[1][2*kk],     wlo1[1] * m8[1][2*kk]);
                    a[2] = cvt2h(wlo0[0] * m8[0][2*kk + 1], wlo1[0] * m8[0][2*kk + 1]);
                    a[3] = cvt2h(wlo0[1] * m8[1][2*kk + 1], wlo1[1] * m8[1][2*kk + 1]);
                    #pragma unroll
                    for (int nt = 0; nt < 4; ++nt) {
                        int m = (kk * 4 + nt) * 2;
                        mma16816(acc[mt][nt], a, breg[m], breg[m + 1]);
                    }
                }
            }
        }
    }

    // ---------------- epilogue: frags -> smem stage -> coalesced global ----------------
    __syncthreads();
    {
        #pragma unroll
        for (int mt = 0; mt < 2; ++mt) {
            int r0 = wm * 32 + mt * 16 + (lid >> 2);
            #pragma unroll
            for (int n8 = 0; n8 < 4; ++n8) {
                int n = wn * 32 + n8 * 8 + (lid & 3) * 2;
                sp[r0 * 132 + n]           = acc[mt][n8][0];
                sp[r0 * 132 + n + 1]       = acc[mt][n8][1];
                sp[(r0 + 8) * 132 + n]     = acc[mt][n8][2];
                sp[(r0 + 8) * 132 + n + 1] = acc[mt][n8][3];
            }
        }
    }
    __syncthreads();

    #pragma unroll
    for (int it = 0; it < 8; ++it) {
        int idx = tid + it * NTHR;
        int s = idx >> 5, u4 = idx & 31;
        float4 v = *(const float4*)(sp + s * 132 + u4 * 4);
        *(float4*)(out + (s0 + s) * NU + u4 * 4) = v;
    }
}

extern "C" void kernel_launch(void* const* d_in, const int* in_sizes, int n_in,
                              void* d_out, int out_size) {
    const float* x  = (const float*)d_in[0];  // [16,1024,256]
    const float* fl = (const float*)d_in[1];  // [256,64,6]
    const float* th = (const float*)d_in[2];  // [64,6]
    const float* lt = (const float*)d_in[3];  // [64,6]
    const float* rs = (const float*)d_in[4];  // [64,128,64]
    float* out      = (float*)d_out;          // [16,1024,128]

    cudaFuncSetAttribute(odt_main, cudaFuncAttributeMaxDynamicSharedMemorySize, SMEM_BYTES);

    prep_sel<<<NTD, 256>>>(fl);
    prep_resp<<<1024, 256>>>(rs, th, lt);
    odt_main<<<NBLK, NTHR, SMEM_BYTES>>>(x, out);
}